// round 13
// baseline (speedup 1.0000x reference)
#include <cuda_runtime.h>
#include <cuda_fp16.h>
#include <math.h>

#define NN 50000
#define NE 800000
#define NT (NE + NN)
#define NB 196      // 196*256 = 50176 >= NN
#define NHALF 24992 // node split for tail pipelining

// ---------------- scratch (static __device__, allocation-free) ----------------
__device__ __half g_h1h [NN * 256];  // layer1 pre-agg features (fp16)
__device__ float  g_h1a [NN * 256];  // layer1 output (post agg + b1 + elu), fp32
__device__ float  g_al1s[NN * 4];
__device__ float  g_al1d[NN * 4];
__device__ float  g_h2 [NN * 64];    // layer2 pre-agg features
__device__ float  g_al2s[NN];
__device__ float  g_al2d[NN];
__device__ float  g_u[NN];           // dot(h2a[n], We[0:64])
__device__ float  g_v[NN];           // dot(h2a[n], We[64:128])
__device__ int    g_deg[NN];         // zero at entry; hist adds; scatter re-zeros
__device__ int    g_off[NN + 1];
__device__ int    g_cur[NN];
__device__ int    g_bsum[NB];
__device__ int    g_bbase[NB];
__device__ int    g_row[NT];         // CSR (by destination): source node per slot

__device__ __forceinline__ float lrelu(float v) { return v > 0.f ? v : 0.2f * v; }
__device__ __forceinline__ float elu1(float v)  { return v > 0.f ? v : expm1f(v); }

// packed 2xfp32 FMA (sm_103a f32x2 pipe; 2x FFMA throughput)
__device__ __forceinline__ float2 ffma2(float2 a, float2 b, float2 c) {
    float2 d;
    asm("fma.rn.f32x2 %0, %1, %2, %3;"
        : "=l"(reinterpret_cast<unsigned long long&>(d))
        : "l"(reinterpret_cast<unsigned long long&>(a)),
          "l"(reinterpret_cast<unsigned long long&>(b)),
          "l"(reinterpret_cast<unsigned long long&>(c)));
    return d;
}

// ---------------- CSR build ----------------
__global__ void k_hist(const int* __restrict__ col) {
    int e = blockIdx.x * blockDim.x + threadIdx.x;
    if (e < NE) atomicAdd(&g_deg[col[e]], 1);
}

__global__ void k_scanA() {   // deg[i]+1 accounts for the self-loop (no deg_init kernel)
    __shared__ int ss[256];
    int b = blockIdx.x, t = threadIdx.x, i = b * 256 + t;
    int d = (i < NN) ? (g_deg[i] + 1) : 0;
    ss[t] = d; __syncthreads();
    for (int o = 1; o < 256; o <<= 1) {
        int v = 0; if (t >= o) v = ss[t - o];
        __syncthreads();
        if (t >= o) ss[t] += v;
        __syncthreads();
    }
    if (i < NN) g_off[i] = ss[t] - d;
    if (t == 255) g_bsum[b] = ss[255];
}

__global__ void k_scanB() {
    __shared__ int ss[256];
    int t = threadIdx.x;
    int v = (t < NB) ? g_bsum[t] : 0;
    ss[t] = v; __syncthreads();
    for (int o = 1; o < 256; o <<= 1) {
        int u = 0; if (t >= o) u = ss[t - o];
        __syncthreads();
        if (t >= o) ss[t] += u;
        __syncthreads();
    }
    if (t < NB) g_bbase[t] = ss[t] - v;
    if (t == NB - 1) g_off[NN] = ss[t];
}

__global__ void k_scanC() {
    int b = blockIdx.x, i = b * 256 + threadIdx.x;
    if (i < NN) {
        int v = g_off[i] + g_bbase[b];
        g_off[i] = v; g_cur[i] = v;
    }
}

__global__ void k_scatter(const int* __restrict__ ei) {
    int e = blockIdx.x * blockDim.x + threadIdx.x;
    if (e >= NT) return;
    int r, c;
    if (e < NE) { r = ei[e]; c = ei[NE + e]; }
    else        { r = c = e - NE; g_deg[e - NE] = 0; }  // reset deg for next replay
    int pos = atomicAdd(&g_cur[c], 1);
    g_row[pos] = r;
}

// --- GEMM1: 128 rows x 64 cols per block (grid = rowTiles*4). Thread tile 8x4.
//     k-chunked smem; fused folded-weight computation (prew) and al1 logits.
__global__ __launch_bounds__(256) void k_gemm1(const float* __restrict__ x,
                                               const float* __restrict__ W1,
                                               const float* __restrict__ a1s,
                                               const float* __restrict__ a1d) {
    __shared__ __align__(16) float xT[32][132];   // [k][row]; 528B stride (16B-aligned)
    __shared__ float4 wsm[32][16];                // [k][col4] current chunk (64 cols)
    __shared__ float  ws[8][65];                  // folded attention weights
    int tid = threadIdx.x;
    int mb = blockIdx.x >> 2, cb = blockIdx.x & 3;
    int row0 = mb * 128;
    int nrows = NN - row0; if (nrows > 128) nrows = 128;
    int ty = tid >> 4, txc = tid & 15;
    int o8 = txc & 7;

    // fused prew (cb==0 blocks only): ws[o][k] = sum_c W1[k,(o&3)*64+c] * a[(o&3)*64+c]
    if (cb == 0) {
        for (int t = tid; t < 512; t += 256) {
            int o = t >> 6, k = t & 63, hh = o & 3;
            const float* a = (o < 4) ? a1s : a1d;
            float s = 0.f;
#pragma unroll 8
            for (int c = 0; c < 64; c++) s += W1[k * 256 + hh * 64 + c] * a[hh * 64 + c];
            ws[o][k] = s;
        }
    }

    float2 acc[8][2];
#pragma unroll
    for (int r = 0; r < 8; r++) { acc[r][0] = make_float2(0.f, 0.f); acc[r][1] = make_float2(0.f, 0.f); }
    float alp[8] = {0, 0, 0, 0, 0, 0, 0, 0};

    for (int kc = 0; kc < 2; kc++) {
        // W chunk: rows [kc*32, +32), cols [cb*64, +64)
        const float4* wg = (const float4*)W1;
        for (int i = tid; i < 32 * 16; i += 256) {
            int k = i >> 4, c4 = i & 15;
            wsm[k][c4] = wg[(kc * 32 + k) * 64 + cb * 16 + c4];
        }
        // x chunk load + transpose (coalesced LDG)
        for (int i = tid; i < nrows * 8; i += 256) {
            int r = i >> 3, f4 = i & 7;
            float4 v = ((const float4*)(x + (size_t)(row0 + r) * 64))[kc * 8 + f4];
            int k = f4 * 4;
            xT[k][r] = v.x; xT[k + 1][r] = v.y; xT[k + 2][r] = v.z; xT[k + 3][r] = v.w;
        }
        __syncthreads();
        if (cb == 0) {
#pragma unroll 8
            for (int k = 0; k < 32; k++) {
                float4 xa = *(const float4*)&xT[k][ty * 8];
                float4 xb = *(const float4*)&xT[k][ty * 8 + 4];
                float4 wv = wsm[k][txc];
                float2 w01 = make_float2(wv.x, wv.y), w23 = make_float2(wv.z, wv.w);
                float wa = ws[o8][kc * 32 + k];
                float xr[8] = {xa.x, xa.y, xa.z, xa.w, xb.x, xb.y, xb.z, xb.w};
#pragma unroll
                for (int r = 0; r < 8; r++) {
                    float2 xx = make_float2(xr[r], xr[r]);
                    acc[r][0] = ffma2(xx, w01, acc[r][0]);
                    acc[r][1] = ffma2(xx, w23, acc[r][1]);
                    alp[r] = fmaf(xr[r], wa, alp[r]);
                }
            }
        } else {
#pragma unroll 8
            for (int k = 0; k < 32; k++) {
                float4 xa = *(const float4*)&xT[k][ty * 8];
                float4 xb = *(const float4*)&xT[k][ty * 8 + 4];
                float4 wv = wsm[k][txc];
                float2 w01 = make_float2(wv.x, wv.y), w23 = make_float2(wv.z, wv.w);
                float xr[8] = {xa.x, xa.y, xa.z, xa.w, xb.x, xb.y, xb.z, xb.w};
#pragma unroll
                for (int r = 0; r < 8; r++) {
                    float2 xx = make_float2(xr[r], xr[r]);
                    acc[r][0] = ffma2(xx, w01, acc[r][0]);
                    acc[r][1] = ffma2(xx, w23, acc[r][1]);
                }
            }
        }
        __syncthreads();
    }

    // store fp16 (8 rows x 4 cols)
#pragma unroll
    for (int r = 0; r < 8; r++) {
        int row = ty * 8 + r;
        if (row < nrows) {
            __half2 h0 = __floats2half2_rn(acc[r][0].x, acc[r][0].y);
            __half2 h1 = __floats2half2_rn(acc[r][1].x, acc[r][1].y);
            uint2 u = make_uint2(*(unsigned*)&h0, *(unsigned*)&h1);
            *(uint2*)&g_h1h[(size_t)(row0 + row) * 256 + cb * 64 + txc * 4] = u;
        }
    }
    // al1 store (cb==0; txc and txc+8 computed duplicates — txc<8 stores)
    if (cb == 0 && txc < 8) {
#pragma unroll
        for (int r = 0; r < 8; r++) {
            int row = ty * 8 + r;
            if (row < nrows) {
                if (o8 < 4) g_al1s[(row0 + row) * 4 + o8] = alp[r];
                else        g_al1d[(row0 + row) * 4 + (o8 - 4)] = alp[r];
            }
        }
    }
}

// ------- layer-1 fused softmax + aggregation (warp/node, 8-wide batched loads) ---
__global__ void k_agg1(const float* __restrict__ b1, int n0, int n1) {
    int n    = n0 + ((blockIdx.x * blockDim.x + threadIdx.x) >> 5);
    int lane = threadIdx.x & 31;
    if (n >= n1) return;
    int s0 = g_off[n], s1 = g_off[n + 1];
    int h = lane >> 3;
    float ad = g_al1d[n * 4 + h];

    float2 acc[4] = {{0,0},{0,0},{0,0},{0,0}};
    float z = 0.f;
    int i = s0;
    for (; i + 8 <= s1; i += 8) {
        int rr[8]; float al[8]; float4 w[8];
#pragma unroll
        for (int u = 0; u < 8; u++) rr[u] = g_row[i + u];
#pragma unroll
        for (int u = 0; u < 8; u++) al[u] = g_al1s[rr[u] * 4 + h];
#pragma unroll
        for (int u = 0; u < 8; u++)
            w[u] = ((const float4*)(g_h1h + (size_t)rr[u] * 256))[lane];
#pragma unroll
        for (int u = 0; u < 8; u++) {
            float e = __expf(lrelu(al[u] + ad));
            z += e;
            const __half2* hp = (const __half2*)&w[u];
            float2 ev = make_float2(e, e);
#pragma unroll
            for (int j = 0; j < 4; j++)
                acc[j] = ffma2(ev, __half22float2(hp[j]), acc[j]);
        }
    }
    for (; i + 4 <= s1; i += 4) {
        int rr[4]; float al[4]; float4 w[4];
#pragma unroll
        for (int u = 0; u < 4; u++) rr[u] = g_row[i + u];
#pragma unroll
        for (int u = 0; u < 4; u++) al[u] = g_al1s[rr[u] * 4 + h];
#pragma unroll
        for (int u = 0; u < 4; u++)
            w[u] = ((const float4*)(g_h1h + (size_t)rr[u] * 256))[lane];
#pragma unroll
        for (int u = 0; u < 4; u++) {
            float e = __expf(lrelu(al[u] + ad));
            z += e;
            const __half2* hp = (const __half2*)&w[u];
            float2 ev = make_float2(e, e);
#pragma unroll
            for (int j = 0; j < 4; j++)
                acc[j] = ffma2(ev, __half22float2(hp[j]), acc[j]);
        }
    }
    for (; i < s1; i++) {
        int r = g_row[i];
        float al = g_al1s[r * 4 + h];
        float4 raw = ((const float4*)(g_h1h + (size_t)r * 256))[lane];
        float e = __expf(lrelu(al + ad));
        z += e;
        const __half2* hp = (const __half2*)&raw;
        float2 ev = make_float2(e, e);
#pragma unroll
        for (int j = 0; j < 4; j++)
            acc[j] = ffma2(ev, __half22float2(hp[j]), acc[j]);
    }
    float inv = 1.f / (z + 1e-16f);
    float4 bv0 = *(const float4*)(b1 + lane * 8);
    float4 bv1 = *(const float4*)(b1 + lane * 8 + 4);
    float4 o0, o1;
    o0.x = elu1(acc[0].x * inv + bv0.x); o0.y = elu1(acc[0].y * inv + bv0.y);
    o0.z = elu1(acc[1].x * inv + bv0.z); o0.w = elu1(acc[1].y * inv + bv0.w);
    o1.x = elu1(acc[2].x * inv + bv1.x); o1.y = elu1(acc[2].y * inv + bv1.y);
    o1.z = elu1(acc[3].x * inv + bv1.z); o1.w = elu1(acc[3].y * inv + bv1.w);
    float4* dst = (float4*)(g_h1a + (size_t)n * 256 + lane * 8);
    dst[0] = o0;
    dst[1] = o1;
}

// ------- GEMM2: register-tiled 64x64 tile, K=256 in 4 chunks; fused al2 ----------
__global__ __launch_bounds__(256) void k_gemm2(const float* __restrict__ W2,
                                               const float* __restrict__ a2s,
                                               const float* __restrict__ a2d,
                                               int base, int count) {
    __shared__ __align__(16) float xT[64][68];   // [k][row], 16B-aligned rows
    __shared__ float4 wsm[64][16];   // [k][col4] (current chunk)
    int tid = threadIdx.x;
    int row0 = base + blockIdx.x * 64;
    int nrows = base + count - row0; if (nrows > 64) nrows = 64;
    int ty = tid >> 4, txc = tid & 15;

    float2 acc[4][2];
#pragma unroll
    for (int r = 0; r < 4; r++) { acc[r][0] = make_float2(0.f, 0.f); acc[r][1] = make_float2(0.f, 0.f); }

    int lr = tid & 63, kg = tid >> 6;
    for (int kc = 0; kc < 4; kc++) {
        const float4* wg = (const float4*)W2;
        for (int i = tid; i < 64 * 16; i += 256) {
            int k = i >> 4, c4 = i & 15;
            wsm[k][c4] = wg[(kc * 64 + k) * 16 + c4];
        }
        if (lr < nrows) {
            const float4* xg = (const float4*)(g_h1a + (size_t)(row0 + lr) * 256) + kc * 16;
#pragma unroll
            for (int kk = 0; kk < 4; kk++) {
                float4 v = xg[kg * 4 + kk];
                int k = (kg * 4 + kk) * 4;
                xT[k][lr] = v.x; xT[k + 1][lr] = v.y; xT[k + 2][lr] = v.z; xT[k + 3][lr] = v.w;
            }
        }
        __syncthreads();
#pragma unroll 8
        for (int k = 0; k < 64; k++) {
            float4 xv = *(const float4*)&xT[k][ty * 4];
            float4 wv = wsm[k][txc];
            float2 w01 = make_float2(wv.x, wv.y), w23 = make_float2(wv.z, wv.w);
            float xr[4] = {xv.x, xv.y, xv.z, xv.w};
#pragma unroll
            for (int r = 0; r < 4; r++) {
                float2 xx = make_float2(xr[r], xr[r]);
                acc[r][0] = ffma2(xx, w01, acc[r][0]);
                acc[r][1] = ffma2(xx, w23, acc[r][1]);
            }
        }
        __syncthreads();
    }

    int c0 = txc * 4;
    float asv[4], adv[4];
#pragma unroll
    for (int c = 0; c < 4; c++) { asv[c] = a2s[c0 + c]; adv[c] = a2d[c0 + c]; }
#pragma unroll
    for (int r = 0; r < 4; r++) {
        int row = ty * 4 + r;
        bool ok = row < nrows;
        float4 hv = make_float4(acc[r][0].x, acc[r][0].y, acc[r][1].x, acc[r][1].y);
        if (ok) *(float4*)&g_h2[(size_t)(row0 + row) * 64 + c0] = hv;
        float ps = hv.x * asv[0] + hv.y * asv[1] + hv.z * asv[2] + hv.w * asv[3];
        float pd = hv.x * adv[0] + hv.y * adv[1] + hv.z * adv[2] + hv.w * adv[3];
#pragma unroll
        for (int off = 8; off; off >>= 1) {
            ps += __shfl_down_sync(0xffffffffu, ps, off);
            pd += __shfl_down_sync(0xffffffffu, pd, off);
        }
        if (txc == 0 && ok) { g_al2s[row0 + row] = ps; g_al2d[row0 + row] = pd; }
    }
}

// --- layer-2 fused softmax + agg + node output + edge factors (warp/node, 8-wide) -
__global__ void k_agg2out(const float* __restrict__ b2, const float* __restrict__ Wn,
                          const float* __restrict__ bn, const float* __restrict__ We,
                          float* __restrict__ out) {
    int n    = (blockIdx.x * blockDim.x + threadIdx.x) >> 5;
    int lane = threadIdx.x & 31;
    if (n >= NN) return;
    int s0 = g_off[n], s1 = g_off[n + 1];
    float ad = g_al2d[n];

    float2 acc = {0.f, 0.f};
    float z = 0.f;
    int i = s0;
    for (; i + 8 <= s1; i += 8) {
        int rr[8]; float al[8]; float2 hh[8];
#pragma unroll
        for (int u = 0; u < 8; u++) rr[u] = g_row[i + u];
#pragma unroll
        for (int u = 0; u < 8; u++) al[u] = g_al2s[rr[u]];
#pragma unroll
        for (int u = 0; u < 8; u++)
            hh[u] = ((const float2*)(g_h2 + (size_t)rr[u] * 64))[lane];
#pragma unroll
        for (int u = 0; u < 8; u++) {
            float e = __expf(lrelu(al[u] + ad));
            z += e;
            acc = ffma2(make_float2(e, e), hh[u], acc);
        }
    }
    for (; i + 4 <= s1; i += 4) {
        int rr[4]; float al[4]; float2 hh[4];
#pragma unroll
        for (int u = 0; u < 4; u++) rr[u] = g_row[i + u];
#pragma unroll
        for (int u = 0; u < 4; u++) al[u] = g_al2s[rr[u]];
#pragma unroll
        for (int u = 0; u < 4; u++)
            hh[u] = ((const float2*)(g_h2 + (size_t)rr[u] * 64))[lane];
#pragma unroll
        for (int u = 0; u < 4; u++) {
            float e = __expf(lrelu(al[u] + ad));
            z += e;
            acc = ffma2(make_float2(e, e), hh[u], acc);
        }
    }
    for (; i < s1; i++) {
        int r = g_row[i];
        float al = g_al2s[r];
        float2 h = ((const float2*)(g_h2 + (size_t)r * 64))[lane];
        float e = __expf(lrelu(al + ad));
        z += e;
        acc = ffma2(make_float2(e, e), h, acc);
    }
    float inv = 1.f / (z + 1e-16f);
    float2 bv = ((const float2*)b2)[lane];
    float2 o;
    o.x = elu1(acc.x * inv + bv.x);
    o.y = elu1(acc.y * inv + bv.y);

    float2 we0 = ((const float2*)We)[lane];
    float2 we1 = ((const float2*)(We + 64))[lane];
    float up = o.x * we0.x + o.y * we0.y;
    float vp = o.x * we1.x + o.y * we1.y;
#pragma unroll
    for (int off = 16; off; off >>= 1) {
        up += __shfl_xor_sync(0xffffffffu, up, off);
        vp += __shfl_xor_sync(0xffffffffu, vp, off);
    }
    if (lane == 0) { g_u[n] = up; g_v[n] = vp; }

    float accn = bn[lane];
#pragma unroll
    for (int kk = 0; kk < 32; kk++) {
        float hx = __shfl_sync(0xffffffffu, o.x, kk);
        float hy = __shfl_sync(0xffffffffu, o.y, kk);
        accn = fmaf(hx, Wn[(2 * kk) * 32 + lane], accn);
        accn = fmaf(hy, Wn[(2 * kk + 1) * 32 + lane], accn);
    }
    out[n * 32 + lane] = accn;
}

// ------- edge output part A -------
__global__ void k_edgeA(const float* __restrict__ ea, const float* __restrict__ We,
                        const float* __restrict__ be, float* __restrict__ out) {
    int e = blockIdx.x * blockDim.x + threadIdx.x;
    if (e >= NE) return;
    const float4* eav = (const float4*)(ea + (size_t)e * 16);
    const float4* wev = (const float4*)(We + 128);
    float4 w0 = wev[0], w1 = wev[1], w2 = wev[2], w3 = wev[3];
    float4 e0 = eav[0], e1 = eav[1], e2 = eav[2], e3 = eav[3];
    float t = be[0];
    t += e0.x * w0.x + e0.y * w0.y + e0.z * w0.z + e0.w * w0.w;
    t += e1.x * w1.x + e1.y * w1.y + e1.z * w1.z + e1.w * w1.w;
    t += e2.x * w2.x + e2.y * w2.y + e2.z * w2.z + e2.w * w2.w;
    t += e3.x * w3.x + e3.y * w3.y + e3.z * w3.z + e3.w * w3.w;
    out[NN * 32 + e] = t;
}

// ------- edge output part B -------
__global__ void k_edgeB(const int* __restrict__ ei, float* __restrict__ out) {
    int e = blockIdx.x * blockDim.x + threadIdx.x;
    if (e >= NE) return;
    int r = ei[e], c = ei[NE + e];
    out[NN * 32 + e] += g_u[r] + g_v[c];
}

// ---------------- launch ----------------
extern "C" void kernel_launch(void* const* d_in, const int* in_sizes, int n_in,
                              void* d_out, int out_size) {
    const float* x   = (const float*)d_in[0];
    const int*   ei  = (const int*)  d_in[1];
    const float* ea  = (const float*)d_in[2];
    const float* W1  = (const float*)d_in[3];
    const float* a1s = (const float*)d_in[4];
    const float* a1d = (const float*)d_in[5];
    const float* b1  = (const float*)d_in[6];
    const float* W2  = (const float*)d_in[7];
    const float* a2s = (const float*)d_in[8];
    const float* a2d = (const float*)d_in[9];
    const float* b2  = (const float*)d_in[10];
    const float* Wn  = (const float*)d_in[11];
    const float* bn  = (const float*)d_in[12];
    const float* We  = (const float*)d_in[13];
    const float* be  = (const float*)d_in[14];
    float* out = (float*)d_out;

    static cudaStream_t s2 = [] {
        cudaStream_t s; cudaStreamCreateWithFlags(&s, cudaStreamNonBlocking); return s;
    }();
    static cudaEvent_t evFork = [] {
        cudaEvent_t e; cudaEventCreateWithFlags(&e, cudaEventDisableTiming); return e;
    }();
    static cudaEvent_t evGemm1 = [] {
        cudaEvent_t e; cudaEventCreateWithFlags(&e, cudaEventDisableTiming); return e;
    }();
    static cudaEvent_t evA = [] {
        cudaEvent_t e; cudaEventCreateWithFlags(&e, cudaEventDisableTiming); return e;
    }();
    static cudaEvent_t evS2 = [] {
        cudaEvent_t e; cudaEventCreateWithFlags(&e, cudaEventDisableTiming); return e;
    }();

    cudaStream_t s0 = 0;

    cudaEventRecord(evFork, s0);
    cudaStreamWaitEvent(s2, evFork, 0);

    // k_gemm1 is the 4th created kernel (ncu capture alignment)
    k_hist  <<<(NE + 255) / 256, 256, 0, s0>>>(ei + NE);                  // 1
    k_scanA <<<NB, 256, 0, s0>>>();                                       // 2
    k_scanB <<<1, 256, 0, s0>>>();                                        // 3
    k_gemm1 <<<((NN + 127) / 128) * 4, 256, 0, s2>>>(x, W1, a1s, a1d);    // 4
    cudaEventRecord(evGemm1, s2);
    k_edgeA <<<(NE + 255) / 256, 256, 0, s2>>>(ea, We, be, out);          // 5
    k_scanC <<<NB, 256, 0, s0>>>();                                       // 6
    k_scatter<<<(NT + 255) / 256, 256, 0, s0>>>(ei);                      // 7

    // tail: pipelined agg1 / gemm2 halves
    cudaStreamWaitEvent(s0, evGemm1, 0);
    k_agg1 <<<(NHALF * 32 + 255) / 256, 256, 0, s0>>>(b1, 0, NHALF);      // 8
    cudaEventRecord(evA, s0);
    k_agg1 <<<((NN - NHALF) * 32 + 255) / 256, 256, 0, s0>>>(b1, NHALF, NN); // 9
    cudaStreamWaitEvent(s2, evA, 0);
    k_gemm2<<<(NHALF + 63) / 64, 256, 0, s2>>>(W2, a2s, a2d, 0, NHALF);   // 10
    cudaEventRecord(evS2, s2);
    k_gemm2<<<(NN - NHALF + 63) / 64, 256, 0, s0>>>(W2, a2s, a2d, NHALF, NN - NHALF); // 11
    cudaStreamWaitEvent(s0, evS2, 0);
    k_agg2out<<<(NN * 32 + 255) / 256, 256, 0, s0>>>(b2, Wn, bn, We, out); // 12
    k_edgeB  <<<(NE + 255) / 256, 256, 0, s0>>>(ei, out);                  // 13
}

// round 14
// speedup vs baseline: 1.1425x; 1.1425x over previous
#include <cuda_runtime.h>
#include <cuda_fp16.h>
#include <math.h>

#define NN 50000
#define NE 800000
#define NT (NE + NN)
#define NB 196      // 196*256 = 50176 >= NN
#define NHALF 24992 // node split for tail pipelining

// ---------------- scratch (static __device__, allocation-free) ----------------
__device__ __half g_h1h [NN * 256];  // layer1 pre-agg features (fp16)
__device__ float  g_h1a [NN * 256];  // layer1 output (post agg + b1 + elu), fp32
__device__ float  g_wt1[8 * 64];     // folded W1@a1 (4 src heads, 4 dst heads)
__device__ float  g_al1s[NN * 4];
__device__ float  g_al1d[NN * 4];
__device__ float  g_h2 [NN * 64];    // layer2 pre-agg features
__device__ float  g_al2s[NN];
__device__ float  g_al2d[NN];
__device__ float  g_u[NN];           // dot(h2a[n], We[0:64])
__device__ float  g_v[NN];           // dot(h2a[n], We[64:128])
__device__ int    g_deg[NN];         // zero at entry; hist adds; scatter re-zeros
__device__ int    g_off[NN + 1];
__device__ int    g_cur[NN];
__device__ int    g_bsum[NB];
__device__ int    g_bbase[NB];
__device__ int    g_row[NT];         // CSR (by destination): source node per slot

__device__ __forceinline__ float lrelu(float v) { return v > 0.f ? v : 0.2f * v; }
__device__ __forceinline__ float elu1(float v)  { return v > 0.f ? v : expm1f(v); }

// packed 2xfp32 FMA (sm_103a f32x2 pipe; 2x FFMA throughput)
__device__ __forceinline__ float2 ffma2(float2 a, float2 b, float2 c) {
    float2 d;
    asm("fma.rn.f32x2 %0, %1, %2, %3;"
        : "=l"(reinterpret_cast<unsigned long long&>(d))
        : "l"(reinterpret_cast<unsigned long long&>(a)),
          "l"(reinterpret_cast<unsigned long long&>(b)),
          "l"(reinterpret_cast<unsigned long long&>(c)));
    return d;
}

// ---------------- CSR build ----------------
__global__ void k_hist(const int* __restrict__ col) {
    int e = blockIdx.x * blockDim.x + threadIdx.x;
    if (e < NE) atomicAdd(&g_deg[col[e]], 1);
}

__global__ void k_scanA() {   // deg[i]+1 accounts for the self-loop (no deg_init kernel)
    __shared__ int ss[256];
    int b = blockIdx.x, t = threadIdx.x, i = b * 256 + t;
    int d = (i < NN) ? (g_deg[i] + 1) : 0;
    ss[t] = d; __syncthreads();
    for (int o = 1; o < 256; o <<= 1) {
        int v = 0; if (t >= o) v = ss[t - o];
        __syncthreads();
        if (t >= o) ss[t] += v;
        __syncthreads();
    }
    if (i < NN) g_off[i] = ss[t] - d;
    if (t == 255) g_bsum[b] = ss[255];
}

__global__ void k_scanB() {
    __shared__ int ss[256];
    int t = threadIdx.x;
    int v = (t < NB) ? g_bsum[t] : 0;
    ss[t] = v; __syncthreads();
    for (int o = 1; o < 256; o <<= 1) {
        int u = 0; if (t >= o) u = ss[t - o];
        __syncthreads();
        if (t >= o) ss[t] += u;
        __syncthreads();
    }
    if (t < NB) g_bbase[t] = ss[t] - v;
    if (t == NB - 1) g_off[NN] = ss[t];
}

__global__ void k_scanC() {
    int b = blockIdx.x, i = b * 256 + threadIdx.x;
    if (i < NN) {
        int v = g_off[i] + g_bbase[b];
        g_off[i] = v; g_cur[i] = v;
    }
}

__global__ void k_scatter(const int* __restrict__ ei) {
    int e = blockIdx.x * blockDim.x + threadIdx.x;
    if (e >= NT) return;
    int r, c;
    if (e < NE) { r = ei[e]; c = ei[NE + e]; }
    else        { r = c = e - NE; g_deg[e - NE] = 0; }  // reset deg for next replay
    int pos = atomicAdd(&g_cur[c], 1);
    g_row[pos] = r;
}

// ---------------- folded attention weights ----------------
__global__ void k_prew(const float* __restrict__ W1, const float* __restrict__ a1s,
                       const float* __restrict__ a1d) {
    int t = threadIdx.x;   // 512 threads, 1 block
    if (t >= 512) return;
    int o = t >> 6, k = t & 63;
    int hh = o & 3;
    const float* a = (o < 4) ? a1s : a1d;
    float s = 0.f;
#pragma unroll 8
    for (int c = 0; c < 64; c++) s += W1[k * 256 + hh * 64 + c] * a[hh * 64 + c];
    g_wt1[o * 64 + k] = s;
}

// --- GEMM1 (R12 proven config): 64 rows x 64 cols/block (grid = rowTiles*4).
//     Thread tile 4x4. x transposed in smem (68-float stride), W tile in smem.
//     fp16 out + fused al1 from precomputed g_wt1.
__global__ __launch_bounds__(256) void k_gemm1(const float* __restrict__ x,
                                               const float* __restrict__ W1) {
    __shared__ __align__(16) float xT[64][68];   // [k][row], 272B row stride
    __shared__ float4 wsm[64][16];   // [k][col4], 64 cols
    __shared__ float  ws[8][65];     // folded attention weights
    int tid = threadIdx.x;
    int mb = blockIdx.x >> 2;
    int cb = blockIdx.x & 3;
    int row0 = mb * 64;
    int nrows = NN - row0; if (nrows > 64) nrows = 64;

    {
        const float4* wg = (const float4*)W1;
        for (int i = tid; i < 64 * 16; i += 256) {
            int k = i >> 4, c4 = i & 15;
            wsm[k][c4] = wg[k * 64 + cb * 16 + c4];
        }
    }
    if (cb == 0)
        for (int i = tid; i < 512; i += 256) ws[i >> 6][i & 63] = g_wt1[i];

    {
        int r = tid & 63, kg = tid >> 6;
        if (r < nrows) {
            const float4* xg = (const float4*)(x + (size_t)(row0 + r) * 64);
#pragma unroll
            for (int kk = 0; kk < 4; kk++) {
                float4 v = xg[kg * 4 + kk];
                int k = (kg * 4 + kk) * 4;
                xT[k][r] = v.x; xT[k + 1][r] = v.y; xT[k + 2][r] = v.z; xT[k + 3][r] = v.w;
            }
        }
    }
    __syncthreads();

    int ty = tid >> 4, txc = tid & 15;
    float2 acc[4][2];
#pragma unroll
    for (int r = 0; r < 4; r++) { acc[r][0] = make_float2(0.f, 0.f); acc[r][1] = make_float2(0.f, 0.f); }
#pragma unroll 8
    for (int k = 0; k < 64; k++) {
        float4 xv = *(const float4*)&xT[k][ty * 4];
        float4 wv = wsm[k][txc];
        float2 w01 = make_float2(wv.x, wv.y), w23 = make_float2(wv.z, wv.w);
        float xr[4] = {xv.x, xv.y, xv.z, xv.w};
#pragma unroll
        for (int r = 0; r < 4; r++) {
            float2 xx = make_float2(xr[r], xr[r]);
            acc[r][0] = ffma2(xx, w01, acc[r][0]);
            acc[r][1] = ffma2(xx, w23, acc[r][1]);
        }
    }
#pragma unroll
    for (int r = 0; r < 4; r++) {
        int row = ty * 4 + r;
        if (row < nrows) {
            __half2 h0 = __floats2half2_rn(acc[r][0].x, acc[r][0].y);
            __half2 h1 = __floats2half2_rn(acc[r][1].x, acc[r][1].y);
            uint2 u = make_uint2(*(unsigned*)&h0, *(unsigned*)&h1);
            *(uint2*)&g_h1h[(size_t)(row0 + row) * 256 + cb * 64 + txc * 4] = u;
        }
    }
    if (cb == 0) {
        for (int t = tid; t < nrows * 8; t += 256) {
            int r = t >> 3, o = t & 7;
            float s = 0.f;
#pragma unroll 16
            for (int k = 0; k < 64; k++) s += xT[k][r] * ws[o][k];
            if (o < 4) g_al1s[(row0 + r) * 4 + o] = s;
            else       g_al1d[(row0 + r) * 4 + (o - 4)] = s;
        }
    }
}

// ------- layer-1 fused softmax + aggregation (warp/node, 8-wide batched loads) ---
__global__ void k_agg1(const float* __restrict__ b1, int n0, int n1) {
    int n    = n0 + ((blockIdx.x * blockDim.x + threadIdx.x) >> 5);
    int lane = threadIdx.x & 31;
    if (n >= n1) return;
    int s0 = g_off[n], s1 = g_off[n + 1];
    int h = lane >> 3;
    float ad = g_al1d[n * 4 + h];

    float2 acc[4] = {{0,0},{0,0},{0,0},{0,0}};
    float z = 0.f;
    int i = s0;
    for (; i + 8 <= s1; i += 8) {
        int rr[8]; float al[8]; float4 w[8];
#pragma unroll
        for (int u = 0; u < 8; u++) rr[u] = g_row[i + u];
#pragma unroll
        for (int u = 0; u < 8; u++) al[u] = g_al1s[rr[u] * 4 + h];
#pragma unroll
        for (int u = 0; u < 8; u++)
            w[u] = ((const float4*)(g_h1h + (size_t)rr[u] * 256))[lane];
#pragma unroll
        for (int u = 0; u < 8; u++) {
            float e = __expf(lrelu(al[u] + ad));
            z += e;
            const __half2* hp = (const __half2*)&w[u];
            float2 ev = make_float2(e, e);
#pragma unroll
            for (int j = 0; j < 4; j++)
                acc[j] = ffma2(ev, __half22float2(hp[j]), acc[j]);
        }
    }
    for (; i + 4 <= s1; i += 4) {
        int rr[4]; float al[4]; float4 w[4];
#pragma unroll
        for (int u = 0; u < 4; u++) rr[u] = g_row[i + u];
#pragma unroll
        for (int u = 0; u < 4; u++) al[u] = g_al1s[rr[u] * 4 + h];
#pragma unroll
        for (int u = 0; u < 4; u++)
            w[u] = ((const float4*)(g_h1h + (size_t)rr[u] * 256))[lane];
#pragma unroll
        for (int u = 0; u < 4; u++) {
            float e = __expf(lrelu(al[u] + ad));
            z += e;
            const __half2* hp = (const __half2*)&w[u];
            float2 ev = make_float2(e, e);
#pragma unroll
            for (int j = 0; j < 4; j++)
                acc[j] = ffma2(ev, __half22float2(hp[j]), acc[j]);
        }
    }
    for (; i < s1; i++) {
        int r = g_row[i];
        float al = g_al1s[r * 4 + h];
        float4 raw = ((const float4*)(g_h1h + (size_t)r * 256))[lane];
        float e = __expf(lrelu(al + ad));
        z += e;
        const __half2* hp = (const __half2*)&raw;
        float2 ev = make_float2(e, e);
#pragma unroll
        for (int j = 0; j < 4; j++)
            acc[j] = ffma2(ev, __half22float2(hp[j]), acc[j]);
    }
    float inv = 1.f / (z + 1e-16f);
    float4 bv0 = *(const float4*)(b1 + lane * 8);
    float4 bv1 = *(const float4*)(b1 + lane * 8 + 4);
    float4 o0, o1;
    o0.x = elu1(acc[0].x * inv + bv0.x); o0.y = elu1(acc[0].y * inv + bv0.y);
    o0.z = elu1(acc[1].x * inv + bv0.z); o0.w = elu1(acc[1].y * inv + bv0.w);
    o1.x = elu1(acc[2].x * inv + bv1.x); o1.y = elu1(acc[2].y * inv + bv1.y);
    o1.z = elu1(acc[3].x * inv + bv1.z); o1.w = elu1(acc[3].y * inv + bv1.w);
    float4* dst = (float4*)(g_h1a + (size_t)n * 256 + lane * 8);
    dst[0] = o0;
    dst[1] = o1;
}

// ------- GEMM2: register-tiled 64x64 tile, K=256 in 4 chunks; fused al2 ----------
__global__ __launch_bounds__(256) void k_gemm2(const float* __restrict__ W2,
                                               const float* __restrict__ a2s,
                                               const float* __restrict__ a2d,
                                               int base, int count) {
    __shared__ __align__(16) float xT[64][68];
    __shared__ float4 wsm[64][16];
    int tid = threadIdx.x;
    int row0 = base + blockIdx.x * 64;
    int nrows = base + count - row0; if (nrows > 64) nrows = 64;
    int ty = tid >> 4, txc = tid & 15;

    float2 acc[4][2];
#pragma unroll
    for (int r = 0; r < 4; r++) { acc[r][0] = make_float2(0.f, 0.f); acc[r][1] = make_float2(0.f, 0.f); }

    int lr = tid & 63, kg = tid >> 6;
    for (int kc = 0; kc < 4; kc++) {
        const float4* wg = (const float4*)W2;
        for (int i = tid; i < 64 * 16; i += 256) {
            int k = i >> 4, c4 = i & 15;
            wsm[k][c4] = wg[(kc * 64 + k) * 16 + c4];
        }
        if (lr < nrows) {
            const float4* xg = (const float4*)(g_h1a + (size_t)(row0 + lr) * 256) + kc * 16;
#pragma unroll
            for (int kk = 0; kk < 4; kk++) {
                float4 v = xg[kg * 4 + kk];
                int k = (kg * 4 + kk) * 4;
                xT[k][lr] = v.x; xT[k + 1][lr] = v.y; xT[k + 2][lr] = v.z; xT[k + 3][lr] = v.w;
            }
        }
        __syncthreads();
#pragma unroll 8
        for (int k = 0; k < 64; k++) {
            float4 xv = *(const float4*)&xT[k][ty * 4];
            float4 wv = wsm[k][txc];
            float2 w01 = make_float2(wv.x, wv.y), w23 = make_float2(wv.z, wv.w);
            float xr[4] = {xv.x, xv.y, xv.z, xv.w};
#pragma unroll
            for (int r = 0; r < 4; r++) {
                float2 xx = make_float2(xr[r], xr[r]);
                acc[r][0] = ffma2(xx, w01, acc[r][0]);
                acc[r][1] = ffma2(xx, w23, acc[r][1]);
            }
        }
        __syncthreads();
    }

    int c0 = txc * 4;
    float asv[4], adv[4];
#pragma unroll
    for (int c = 0; c < 4; c++) { asv[c] = a2s[c0 + c]; adv[c] = a2d[c0 + c]; }
#pragma unroll
    for (int r = 0; r < 4; r++) {
        int row = ty * 4 + r;
        bool ok = row < nrows;
        float4 hv = make_float4(acc[r][0].x, acc[r][0].y, acc[r][1].x, acc[r][1].y);
        if (ok) *(float4*)&g_h2[(size_t)(row0 + row) * 64 + c0] = hv;
        float ps = hv.x * asv[0] + hv.y * asv[1] + hv.z * asv[2] + hv.w * asv[3];
        float pd = hv.x * adv[0] + hv.y * adv[1] + hv.z * adv[2] + hv.w * adv[3];
#pragma unroll
        for (int off = 8; off; off >>= 1) {
            ps += __shfl_down_sync(0xffffffffu, ps, off);
            pd += __shfl_down_sync(0xffffffffu, pd, off);
        }
        if (txc == 0 && ok) { g_al2s[row0 + row] = ps; g_al2d[row0 + row] = pd; }
    }
}

// --- layer-2 fused softmax + agg + node output + edge factors (warp/node, 8-wide) -
__global__ void k_agg2out(const float* __restrict__ b2, const float* __restrict__ Wn,
                          const float* __restrict__ bn, const float* __restrict__ We,
                          float* __restrict__ out) {
    int n    = (blockIdx.x * blockDim.x + threadIdx.x) >> 5;
    int lane = threadIdx.x & 31;
    if (n >= NN) return;
    int s0 = g_off[n], s1 = g_off[n + 1];
    float ad = g_al2d[n];

    float2 acc = {0.f, 0.f};
    float z = 0.f;
    int i = s0;
    for (; i + 8 <= s1; i += 8) {
        int rr[8]; float al[8]; float2 hh[8];
#pragma unroll
        for (int u = 0; u < 8; u++) rr[u] = g_row[i + u];
#pragma unroll
        for (int u = 0; u < 8; u++) al[u] = g_al2s[rr[u]];
#pragma unroll
        for (int u = 0; u < 8; u++)
            hh[u] = ((const float2*)(g_h2 + (size_t)rr[u] * 64))[lane];
#pragma unroll
        for (int u = 0; u < 8; u++) {
            float e = __expf(lrelu(al[u] + ad));
            z += e;
            acc = ffma2(make_float2(e, e), hh[u], acc);
        }
    }
    for (; i + 4 <= s1; i += 4) {
        int rr[4]; float al[4]; float2 hh[4];
#pragma unroll
        for (int u = 0; u < 4; u++) rr[u] = g_row[i + u];
#pragma unroll
        for (int u = 0; u < 4; u++) al[u] = g_al2s[rr[u]];
#pragma unroll
        for (int u = 0; u < 4; u++)
            hh[u] = ((const float2*)(g_h2 + (size_t)rr[u] * 64))[lane];
#pragma unroll
        for (int u = 0; u < 4; u++) {
            float e = __expf(lrelu(al[u] + ad));
            z += e;
            acc = ffma2(make_float2(e, e), hh[u], acc);
        }
    }
    for (; i < s1; i++) {
        int r = g_row[i];
        float al = g_al2s[r];
        float2 h = ((const float2*)(g_h2 + (size_t)r * 64))[lane];
        float e = __expf(lrelu(al + ad));
        z += e;
        acc = ffma2(make_float2(e, e), h, acc);
    }
    float inv = 1.f / (z + 1e-16f);
    float2 bv = ((const float2*)b2)[lane];
    float2 o;
    o.x = elu1(acc.x * inv + bv.x);
    o.y = elu1(acc.y * inv + bv.y);

    float2 we0 = ((const float2*)We)[lane];
    float2 we1 = ((const float2*)(We + 64))[lane];
    float up = o.x * we0.x + o.y * we0.y;
    float vp = o.x * we1.x + o.y * we1.y;
#pragma unroll
    for (int off = 16; off; off >>= 1) {
        up += __shfl_xor_sync(0xffffffffu, up, off);
        vp += __shfl_xor_sync(0xffffffffu, vp, off);
    }
    if (lane == 0) { g_u[n] = up; g_v[n] = vp; }

    float accn = bn[lane];
#pragma unroll
    for (int kk = 0; kk < 32; kk++) {
        float hx = __shfl_sync(0xffffffffu, o.x, kk);
        float hy = __shfl_sync(0xffffffffu, o.y, kk);
        accn = fmaf(hx, Wn[(2 * kk) * 32 + lane], accn);
        accn = fmaf(hy, Wn[(2 * kk + 1) * 32 + lane], accn);
    }
    out[n * 32 + lane] = accn;
}

// ------- edge output part A -------
__global__ void k_edgeA(const float* __restrict__ ea, const float* __restrict__ We,
                        const float* __restrict__ be, float* __restrict__ out) {
    int e = blockIdx.x * blockDim.x + threadIdx.x;
    if (e >= NE) return;
    const float4* eav = (const float4*)(ea + (size_t)e * 16);
    const float4* wev = (const float4*)(We + 128);
    float4 w0 = wev[0], w1 = wev[1], w2 = wev[2], w3 = wev[3];
    float4 e0 = eav[0], e1 = eav[1], e2 = eav[2], e3 = eav[3];
    float t = be[0];
    t += e0.x * w0.x + e0.y * w0.y + e0.z * w0.z + e0.w * w0.w;
    t += e1.x * w1.x + e1.y * w1.y + e1.z * w1.z + e1.w * w1.w;
    t += e2.x * w2.x + e2.y * w2.y + e2.z * w2.z + e2.w * w2.w;
    t += e3.x * w3.x + e3.y * w3.y + e3.z * w3.z + e3.w * w3.w;
    out[NN * 32 + e] = t;
}

// ------- edge output part B -------
__global__ void k_edgeB(const int* __restrict__ ei, float* __restrict__ out) {
    int e = blockIdx.x * blockDim.x + threadIdx.x;
    if (e >= NE) return;
    int r = ei[e], c = ei[NE + e];
    out[NN * 32 + e] += g_u[r] + g_v[c];
}

// ---------------- launch ----------------
extern "C" void kernel_launch(void* const* d_in, const int* in_sizes, int n_in,
                              void* d_out, int out_size) {
    const float* x   = (const float*)d_in[0];
    const int*   ei  = (const int*)  d_in[1];
    const float* ea  = (const float*)d_in[2];
    const float* W1  = (const float*)d_in[3];
    const float* a1s = (const float*)d_in[4];
    const float* a1d = (const float*)d_in[5];
    const float* b1  = (const float*)d_in[6];
    const float* W2  = (const float*)d_in[7];
    const float* a2s = (const float*)d_in[8];
    const float* a2d = (const float*)d_in[9];
    const float* b2  = (const float*)d_in[10];
    const float* Wn  = (const float*)d_in[11];
    const float* bn  = (const float*)d_in[12];
    const float* We  = (const float*)d_in[13];
    const float* be  = (const float*)d_in[14];
    float* out = (float*)d_out;

    static cudaStream_t s2 = [] {
        cudaStream_t s; cudaStreamCreateWithFlags(&s, cudaStreamNonBlocking); return s;
    }();
    static cudaEvent_t evFork = [] {
        cudaEvent_t e; cudaEventCreateWithFlags(&e, cudaEventDisableTiming); return e;
    }();
    static cudaEvent_t evGemm1 = [] {
        cudaEvent_t e; cudaEventCreateWithFlags(&e, cudaEventDisableTiming); return e;
    }();
    static cudaEvent_t evA = [] {
        cudaEvent_t e; cudaEventCreateWithFlags(&e, cudaEventDisableTiming); return e;
    }();
    static cudaEvent_t evS2 = [] {
        cudaEvent_t e; cudaEventCreateWithFlags(&e, cudaEventDisableTiming); return e;
    }();

    cudaStream_t s0 = 0;

    cudaEventRecord(evFork, s0);
    cudaStreamWaitEvent(s2, evFork, 0);

    // k_gemm1 is the 4th created kernel (ncu capture alignment)
    k_hist  <<<(NE + 255) / 256, 256, 0, s0>>>(ei + NE);                  // 1
    k_scanA <<<NB, 256, 0, s0>>>();                                       // 2
    k_prew  <<<1, 512, 0, s2>>>(W1, a1s, a1d);                            // 3
    k_gemm1 <<<((NN + 63) / 64) * 4, 256, 0, s2>>>(x, W1);                // 4
    cudaEventRecord(evGemm1, s2);
    k_edgeA <<<(NE + 255) / 256, 256, 0, s2>>>(ea, We, be, out);          // 5
    k_scanB <<<1, 256, 0, s0>>>();                                        // 6
    k_scanC <<<NB, 256, 0, s0>>>();                                       // 7
    k_scatter<<<(NT + 255) / 256, 256, 0, s0>>>(ei);                      // 8

    // tail: pipelined agg1 / gemm2 halves
    cudaStreamWaitEvent(s0, evGemm1, 0);
    k_agg1 <<<(NHALF * 32 + 255) / 256, 256, 0, s0>>>(b1, 0, NHALF);      // 9
    cudaEventRecord(evA, s0);
    k_agg1 <<<((NN - NHALF) * 32 + 255) / 256, 256, 0, s0>>>(b1, NHALF, NN); // 10
    cudaStreamWaitEvent(s2, evA, 0);
    k_gemm2<<<(NHALF + 63) / 64, 256, 0, s2>>>(W2, a2s, a2d, 0, NHALF);   // 11
    cudaEventRecord(evS2, s2);
    k_gemm2<<<(NN - NHALF + 63) / 64, 256, 0, s0>>>(W2, a2s, a2d, NHALF, NN - NHALF); // 12
    cudaStreamWaitEvent(s0, evS2, 0);
    k_agg2out<<<(NN * 32 + 255) / 256, 256, 0, s0>>>(b2, Wn, bn, We, out); // 13
    k_edgeB  <<<(NE + 255) / 256, 256, 0, s0>>>(ei, out);                  // 14
}

// round 15
// speedup vs baseline: 1.1426x; 1.0001x over previous
#include <cuda_runtime.h>
#include <cuda_fp16.h>
#include <math.h>

#define NN 50000
#define NE 800000
#define NT (NE + NN)
#define NB 196      // 196*256 = 50176 >= NN
#define NHALF 24992 // node split for tail pipelining

// ---------------- scratch (static __device__, allocation-free) ----------------
__device__ __half g_xh  [NN * 64];   // x in fp16 (HMMA A operand)
__device__ __half g_w1h [256 * 64];  // W1 transposed fp16: g_w1h[n*64+k] = W1[k,n]
__device__ __half g_h1h [NN * 256];  // layer1 pre-agg features (fp16)
__device__ float  g_h1a [NN * 256];  // layer1 output (post agg + b1 + elu), fp32
__device__ float  g_wt1[8 * 64];     // folded W1@a1 (4 src heads, 4 dst heads)
__device__ float  g_al1s[NN * 4];
__device__ float  g_al1d[NN * 4];
__device__ float  g_h2 [NN * 64];    // layer2 pre-agg features
__device__ float  g_al2s[NN];
__device__ float  g_al2d[NN];
__device__ float  g_u[NN];           // dot(h2a[n], We[0:64])
__device__ float  g_v[NN];           // dot(h2a[n], We[64:128])
__device__ int    g_deg[NN];         // zero at entry; hist adds; scatter re-zeros
__device__ int    g_off[NN + 1];
__device__ int    g_cur[NN];
__device__ int    g_bsum[NB];
__device__ int    g_bbase[NB];
__device__ int    g_row[NT];         // CSR (by destination): source node per slot

__device__ __forceinline__ float lrelu(float v) { return v > 0.f ? v : 0.2f * v; }
__device__ __forceinline__ float elu1(float v)  { return v > 0.f ? v : expm1f(v); }

// packed 2xfp32 FMA (sm_103a f32x2 pipe; 2x FFMA throughput)
__device__ __forceinline__ float2 ffma2(float2 a, float2 b, float2 c) {
    float2 d;
    asm("fma.rn.f32x2 %0, %1, %2, %3;"
        : "=l"(reinterpret_cast<unsigned long long&>(d))
        : "l"(reinterpret_cast<unsigned long long&>(a)),
          "l"(reinterpret_cast<unsigned long long&>(b)),
          "l"(reinterpret_cast<unsigned long long&>(c)));
    return d;
}

// ---------------- CSR build ----------------
__global__ void k_hist(const int* __restrict__ col) {
    int e = blockIdx.x * blockDim.x + threadIdx.x;
    if (e < NE) atomicAdd(&g_deg[col[e]], 1);
}

__global__ void k_scanA() {   // deg[i]+1 accounts for the self-loop
    __shared__ int ss[256];
    int b = blockIdx.x, t = threadIdx.x, i = b * 256 + t;
    int d = (i < NN) ? (g_deg[i] + 1) : 0;
    ss[t] = d; __syncthreads();
    for (int o = 1; o < 256; o <<= 1) {
        int v = 0; if (t >= o) v = ss[t - o];
        __syncthreads();
        if (t >= o) ss[t] += v;
        __syncthreads();
    }
    if (i < NN) g_off[i] = ss[t] - d;
    if (t == 255) g_bsum[b] = ss[255];
}

__global__ void k_scanB() {
    __shared__ int ss[256];
    int t = threadIdx.x;
    int v = (t < NB) ? g_bsum[t] : 0;
    ss[t] = v; __syncthreads();
    for (int o = 1; o < 256; o <<= 1) {
        int u = 0; if (t >= o) u = ss[t - o];
        __syncthreads();
        if (t >= o) ss[t] += u;
        __syncthreads();
    }
    if (t < NB) g_bbase[t] = ss[t] - v;
    if (t == NB - 1) g_off[NN] = ss[t];
}

__global__ void k_scanC() {
    int b = blockIdx.x, i = b * 256 + threadIdx.x;
    if (i < NN) {
        int v = g_off[i] + g_bbase[b];
        g_off[i] = v; g_cur[i] = v;
    }
}

__global__ void k_scatter(const int* __restrict__ ei) {
    int e = blockIdx.x * blockDim.x + threadIdx.x;
    if (e >= NT) return;
    int r, c;
    if (e < NE) { r = ei[e]; c = ei[NE + e]; }
    else        { r = c = e - NE; g_deg[e - NE] = 0; }  // reset deg for next replay
    int pos = atomicAdd(&g_cur[c], 1);
    g_row[pos] = r;
}

// ------- prew: folded attention weights + fp16 transposed W1 (grid 8 x 256) ------
__global__ void k_prew(const float* __restrict__ W1, const float* __restrict__ a1s,
                       const float* __restrict__ a1d) {
    int t = blockIdx.x * 256 + threadIdx.x;   // 2048 threads
    if (t < 512) {
        int o = t >> 6, k = t & 63, hh = o & 3;
        const float* a = (o < 4) ? a1s : a1d;
        float s = 0.f;
#pragma unroll 8
        for (int c = 0; c < 64; c++) s += W1[k * 256 + hh * 64 + c] * a[hh * 64 + c];
        g_wt1[o * 64 + k] = s;
    }
    for (int i = t; i < 256 * 64; i += 2048) {
        int n = i >> 6, kk = i & 63;
        g_w1h[i] = __float2half_rn(W1[kk * 256 + n]);
    }
}

// ------- xcvt: x -> fp16 + fp32 al1 logits (warp per node) -------
__global__ __launch_bounds__(256) void k_xcvt(const float* __restrict__ x) {
    __shared__ float ws[8][65];
    int tid = threadIdx.x;
    for (int i = tid; i < 512; i += 256) ws[i >> 6][i & 63] = g_wt1[i];
    __syncthreads();
    int n = blockIdx.x * 8 + (tid >> 5);
    int lane = tid & 31;
    if (n >= NN) return;
    float2 xv = ((const float2*)(x + (size_t)n * 64))[lane];
    ((half2*)(g_xh + (size_t)n * 64))[lane] = __floats2half2_rn(xv.x, xv.y);
    float p[8];
#pragma unroll
    for (int o = 0; o < 8; o++)
        p[o] = xv.x * ws[o][2 * lane] + xv.y * ws[o][2 * lane + 1];
#pragma unroll
    for (int off = 16; off; off >>= 1)
#pragma unroll
        for (int o = 0; o < 8; o++) p[o] += __shfl_xor_sync(0xffffffffu, p[o], off);
    if (lane == 0) {
        *(float4*)&g_al1s[n * 4] = make_float4(p[0], p[1], p[2], p[3]);
        *(float4*)&g_al1d[n * 4] = make_float4(p[4], p[5], p[6], p[7]);
    }
}

// --- GEMM1 via HMMA: h1h = xh[N,64] @ W1[64,256], fp32 accum, fp16 out.
//     Block: 128 rows x 64 cols (grid = rowTiles*4). Warp: 16 rows x 64 cols.
//     mma.sync.m16n8k16: A row-major from g_xh, B col-major from g_w1h.
__global__ __launch_bounds__(256) void k_gemm1() {
    int tid = threadIdx.x, wid = tid >> 5, lane = tid & 31;
    int mb = blockIdx.x >> 2, cb = blockIdx.x & 3;
    int row0 = mb * 128 + wid * 16;
    int g = lane >> 2, q = lane & 3;
    int rowA = row0 + g, rowB = row0 + g + 8;
    bool okA = rowA < NN, okB = rowB < NN;
    const __half* xa = g_xh + (size_t)rowA * 64;
    const __half* xb = g_xh + (size_t)rowB * 64;

    float c[8][4];
#pragma unroll
    for (int nt = 0; nt < 8; nt++)
#pragma unroll
        for (int j = 0; j < 4; j++) c[nt][j] = 0.f;

#pragma unroll
    for (int kt = 0; kt < 4; kt++) {
        int kb = kt * 16 + 2 * q;
        unsigned a0 = 0, a1 = 0, a2 = 0, a3 = 0;
        if (okA) { a0 = *(const unsigned*)(xa + kb); a2 = *(const unsigned*)(xa + kb + 8); }
        if (okB) { a1 = *(const unsigned*)(xb + kb); a3 = *(const unsigned*)(xb + kb + 8); }
#pragma unroll
        for (int nt = 0; nt < 8; nt++) {
            int ncol = cb * 64 + nt * 8 + g;
            const __half* bp = g_w1h + ncol * 64 + kt * 16 + 2 * q;
            unsigned b0 = *(const unsigned*)bp;
            unsigned b1 = *(const unsigned*)(bp + 8);
            asm volatile(
                "mma.sync.aligned.m16n8k16.row.col.f32.f16.f16.f32 "
                "{%0,%1,%2,%3}, {%4,%5,%6,%7}, {%8,%9}, {%0,%1,%2,%3};"
                : "+f"(c[nt][0]), "+f"(c[nt][1]), "+f"(c[nt][2]), "+f"(c[nt][3])
                : "r"(a0), "r"(a1), "r"(a2), "r"(a3), "r"(b0), "r"(b1));
        }
    }
#pragma unroll
    for (int nt = 0; nt < 8; nt++) {
        int colb = cb * 64 + nt * 8 + 2 * q;
        if (okA) {
            __half2 h = __floats2half2_rn(c[nt][0], c[nt][1]);
            *(unsigned*)&g_h1h[(size_t)rowA * 256 + colb] = *(unsigned*)&h;
        }
        if (okB) {
            __half2 h = __floats2half2_rn(c[nt][2], c[nt][3]);
            *(unsigned*)&g_h1h[(size_t)rowB * 256 + colb] = *(unsigned*)&h;
        }
    }
}

// ------- layer-1 fused softmax + aggregation (warp/node, 8-wide batched loads) ---
__global__ void k_agg1(const float* __restrict__ b1, int n0, int n1) {
    int n    = n0 + ((blockIdx.x * blockDim.x + threadIdx.x) >> 5);
    int lane = threadIdx.x & 31;
    if (n >= n1) return;
    int s0 = g_off[n], s1 = g_off[n + 1];
    int h = lane >> 3;
    float ad = g_al1d[n * 4 + h];

    float2 acc[4] = {{0,0},{0,0},{0,0},{0,0}};
    float z = 0.f;
    int i = s0;
    for (; i + 8 <= s1; i += 8) {
        int rr[8]; float al[8]; float4 w[8];
#pragma unroll
        for (int u = 0; u < 8; u++) rr[u] = g_row[i + u];
#pragma unroll
        for (int u = 0; u < 8; u++) al[u] = g_al1s[rr[u] * 4 + h];
#pragma unroll
        for (int u = 0; u < 8; u++)
            w[u] = ((const float4*)(g_h1h + (size_t)rr[u] * 256))[lane];
#pragma unroll
        for (int u = 0; u < 8; u++) {
            float e = __expf(lrelu(al[u] + ad));
            z += e;
            const __half2* hp = (const __half2*)&w[u];
            float2 ev = make_float2(e, e);
#pragma unroll
            for (int j = 0; j < 4; j++)
                acc[j] = ffma2(ev, __half22float2(hp[j]), acc[j]);
        }
    }
    for (; i + 4 <= s1; i += 4) {
        int rr[4]; float al[4]; float4 w[4];
#pragma unroll
        for (int u = 0; u < 4; u++) rr[u] = g_row[i + u];
#pragma unroll
        for (int u = 0; u < 4; u++) al[u] = g_al1s[rr[u] * 4 + h];
#pragma unroll
        for (int u = 0; u < 4; u++)
            w[u] = ((const float4*)(g_h1h + (size_t)rr[u] * 256))[lane];
#pragma unroll
        for (int u = 0; u < 4; u++) {
            float e = __expf(lrelu(al[u] + ad));
            z += e;
            const __half2* hp = (const __half2*)&w[u];
            float2 ev = make_float2(e, e);
#pragma unroll
            for (int j = 0; j < 4; j++)
                acc[j] = ffma2(ev, __half22float2(hp[j]), acc[j]);
        }
    }
    for (; i < s1; i++) {
        int r = g_row[i];
        float al = g_al1s[r * 4 + h];
        float4 raw = ((const float4*)(g_h1h + (size_t)r * 256))[lane];
        float e = __expf(lrelu(al + ad));
        z += e;
        const __half2* hp = (const __half2*)&raw;
        float2 ev = make_float2(e, e);
#pragma unroll
        for (int j = 0; j < 4; j++)
            acc[j] = ffma2(ev, __half22float2(hp[j]), acc[j]);
    }
    float inv = 1.f / (z + 1e-16f);
    float4 bv0 = *(const float4*)(b1 + lane * 8);
    float4 bv1 = *(const float4*)(b1 + lane * 8 + 4);
    float4 o0, o1;
    o0.x = elu1(acc[0].x * inv + bv0.x); o0.y = elu1(acc[0].y * inv + bv0.y);
    o0.z = elu1(acc[1].x * inv + bv0.z); o0.w = elu1(acc[1].y * inv + bv0.w);
    o1.x = elu1(acc[2].x * inv + bv1.x); o1.y = elu1(acc[2].y * inv + bv1.y);
    o1.z = elu1(acc[3].x * inv + bv1.z); o1.w = elu1(acc[3].y * inv + bv1.w);
    float4* dst = (float4*)(g_h1a + (size_t)n * 256 + lane * 8);
    dst[0] = o0;
    dst[1] = o1;
}

// ------- GEMM2: register-tiled 64x64 tile, K=256 in 4 chunks; fused al2 ----------
__global__ __launch_bounds__(256) void k_gemm2(const float* __restrict__ W2,
                                               const float* __restrict__ a2s,
                                               const float* __restrict__ a2d,
                                               int base, int count) {
    __shared__ __align__(16) float xT[64][68];
    __shared__ float4 wsm[64][16];
    int tid = threadIdx.x;
    int row0 = base + blockIdx.x * 64;
    int nrows = base + count - row0; if (nrows > 64) nrows = 64;
    int ty = tid >> 4, txc = tid & 15;

    float2 acc[4][2];
#pragma unroll
    for (int r = 0; r < 4; r++) { acc[r][0] = make_float2(0.f, 0.f); acc[r][1] = make_float2(0.f, 0.f); }

    int lr = tid & 63, kg = tid >> 6;
    for (int kc = 0; kc < 4; kc++) {
        const float4* wg = (const float4*)W2;
        for (int i = tid; i < 64 * 16; i += 256) {
            int k = i >> 4, c4 = i & 15;
            wsm[k][c4] = wg[(kc * 64 + k) * 16 + c4];
        }
        if (lr < nrows) {
            const float4* xg = (const float4*)(g_h1a + (size_t)(row0 + lr) * 256) + kc * 16;
#pragma unroll
            for (int kk = 0; kk < 4; kk++) {
                float4 v = xg[kg * 4 + kk];
                int k = (kg * 4 + kk) * 4;
                xT[k][lr] = v.x; xT[k + 1][lr] = v.y; xT[k + 2][lr] = v.z; xT[k + 3][lr] = v.w;
            }
        }
        __syncthreads();
#pragma unroll 8
        for (int k = 0; k < 64; k++) {
            float4 xv = *(const float4*)&xT[k][ty * 4];
            float4 wv = wsm[k][txc];
            float2 w01 = make_float2(wv.x, wv.y), w23 = make_float2(wv.z, wv.w);
            float xr[4] = {xv.x, xv.y, xv.z, xv.w};
#pragma unroll
            for (int r = 0; r < 4; r++) {
                float2 xx = make_float2(xr[r], xr[r]);
                acc[r][0] = ffma2(xx, w01, acc[r][0]);
                acc[r][1] = ffma2(xx, w23, acc[r][1]);
            }
        }
        __syncthreads();
    }

    int c0 = txc * 4;
    float asv[4], adv[4];
#pragma unroll
    for (int c = 0; c < 4; c++) { asv[c] = a2s[c0 + c]; adv[c] = a2d[c0 + c]; }
#pragma unroll
    for (int r = 0; r < 4; r++) {
        int row = ty * 4 + r;
        bool ok = row < nrows;
        float4 hv = make_float4(acc[r][0].x, acc[r][0].y, acc[r][1].x, acc[r][1].y);
        if (ok) *(float4*)&g_h2[(size_t)(row0 + row) * 64 + c0] = hv;
        float ps = hv.x * asv[0] + hv.y * asv[1] + hv.z * asv[2] + hv.w * asv[3];
        float pd = hv.x * adv[0] + hv.y * adv[1] + hv.z * adv[2] + hv.w * adv[3];
#pragma unroll
        for (int off = 8; off; off >>= 1) {
            ps += __shfl_down_sync(0xffffffffu, ps, off);
            pd += __shfl_down_sync(0xffffffffu, pd, off);
        }
        if (txc == 0 && ok) { g_al2s[row0 + row] = ps; g_al2d[row0 + row] = pd; }
    }
}

// --- layer-2 fused softmax + agg + node output + edge factors (warp/node, 8-wide) -
__global__ void k_agg2out(const float* __restrict__ b2, const float* __restrict__ Wn,
                          const float* __restrict__ bn, const float* __restrict__ We,
                          float* __restrict__ out) {
    int n    = (blockIdx.x * blockDim.x + threadIdx.x) >> 5;
    int lane = threadIdx.x & 31;
    if (n >= NN) return;
    int s0 = g_off[n], s1 = g_off[n + 1];
    float ad = g_al2d[n];

    float2 acc = {0.f, 0.f};
    float z = 0.f;
    int i = s0;
    for (; i + 8 <= s1; i += 8) {
        int rr[8]; float al[8]; float2 hh[8];
#pragma unroll
        for (int u = 0; u < 8; u++) rr[u] = g_row[i + u];
#pragma unroll
        for (int u = 0; u < 8; u++) al[u] = g_al2s[rr[u]];
#pragma unroll
        for (int u = 0; u < 8; u++)
            hh[u] = ((const float2*)(g_h2 + (size_t)rr[u] * 64))[lane];
#pragma unroll
        for (int u = 0; u < 8; u++) {
            float e = __expf(lrelu(al[u] + ad));
            z += e;
            acc = ffma2(make_float2(e, e), hh[u], acc);
        }
    }
    for (; i + 4 <= s1; i += 4) {
        int rr[4]; float al[4]; float2 hh[4];
#pragma unroll
        for (int u = 0; u < 4; u++) rr[u] = g_row[i + u];
#pragma unroll
        for (int u = 0; u < 4; u++) al[u] = g_al2s[rr[u]];
#pragma unroll
        for (int u = 0; u < 4; u++)
            hh[u] = ((const float2*)(g_h2 + (size_t)rr[u] * 64))[lane];
#pragma unroll
        for (int u = 0; u < 4; u++) {
            float e = __expf(lrelu(al[u] + ad));
            z += e;
            acc = ffma2(make_float2(e, e), hh[u], acc);
        }
    }
    for (; i < s1; i++) {
        int r = g_row[i];
        float al = g_al2s[r];
        float2 h = ((const float2*)(g_h2 + (size_t)r * 64))[lane];
        float e = __expf(lrelu(al + ad));
        z += e;
        acc = ffma2(make_float2(e, e), h, acc);
    }
    float inv = 1.f / (z + 1e-16f);
    float2 bv = ((const float2*)b2)[lane];
    float2 o;
    o.x = elu1(acc.x * inv + bv.x);
    o.y = elu1(acc.y * inv + bv.y);

    float2 we0 = ((const float2*)We)[lane];
    float2 we1 = ((const float2*)(We + 64))[lane];
    float up = o.x * we0.x + o.y * we0.y;
    float vp = o.x * we1.x + o.y * we1.y;
#pragma unroll
    for (int off = 16; off; off >>= 1) {
        up += __shfl_xor_sync(0xffffffffu, up, off);
        vp += __shfl_xor_sync(0xffffffffu, vp, off);
    }
    if (lane == 0) { g_u[n] = up; g_v[n] = vp; }

    float accn = bn[lane];
#pragma unroll
    for (int kk = 0; kk < 32; kk++) {
        float hx = __shfl_sync(0xffffffffu, o.x, kk);
        float hy = __shfl_sync(0xffffffffu, o.y, kk);
        accn = fmaf(hx, Wn[(2 * kk) * 32 + lane], accn);
        accn = fmaf(hy, Wn[(2 * kk + 1) * 32 + lane], accn);
    }
    out[n * 32 + lane] = accn;
}

// ------- edge output part A -------
__global__ void k_edgeA(const float* __restrict__ ea, const float* __restrict__ We,
                        const float* __restrict__ be, float* __restrict__ out) {
    int e = blockIdx.x * blockDim.x + threadIdx.x;
    if (e >= NE) return;
    const float4* eav = (const float4*)(ea + (size_t)e * 16);
    const float4* wev = (const float4*)(We + 128);
    float4 w0 = wev[0], w1 = wev[1], w2 = wev[2], w3 = wev[3];
    float4 e0 = eav[0], e1 = eav[1], e2 = eav[2], e3 = eav[3];
    float t = be[0];
    t += e0.x * w0.x + e0.y * w0.y + e0.z * w0.z + e0.w * w0.w;
    t += e1.x * w1.x + e1.y * w1.y + e1.z * w1.z + e1.w * w1.w;
    t += e2.x * w2.x + e2.y * w2.y + e2.z * w2.z + e2.w * w2.w;
    t += e3.x * w3.x + e3.y * w3.y + e3.z * w3.z + e3.w * w3.w;
    out[NN * 32 + e] = t;
}

// ------- edge output part B -------
__global__ void k_edgeB(const int* __restrict__ ei, float* __restrict__ out) {
    int e = blockIdx.x * blockDim.x + threadIdx.x;
    if (e >= NE) return;
    int r = ei[e], c = ei[NE + e];
    out[NN * 32 + e] += g_u[r] + g_v[c];
}

// ---------------- launch ----------------
extern "C" void kernel_launch(void* const* d_in, const int* in_sizes, int n_in,
                              void* d_out, int out_size) {
    const float* x   = (const float*)d_in[0];
    const int*   ei  = (const int*)  d_in[1];
    const float* ea  = (const float*)d_in[2];
    const float* W1  = (const float*)d_in[3];
    const float* a1s = (const float*)d_in[4];
    const float* a1d = (const float*)d_in[5];
    const float* b1  = (const float*)d_in[6];
    const float* W2  = (const float*)d_in[7];
    const float* a2s = (const float*)d_in[8];
    const float* a2d = (const float*)d_in[9];
    const float* b2  = (const float*)d_in[10];
    const float* Wn  = (const float*)d_in[11];
    const float* bn  = (const float*)d_in[12];
    const float* We  = (const float*)d_in[13];
    const float* be  = (const float*)d_in[14];
    float* out = (float*)d_out;

    static cudaStream_t s2 = [] {
        cudaStream_t s; cudaStreamCreateWithFlags(&s, cudaStreamNonBlocking); return s;
    }();
    static cudaEvent_t evFork = [] {
        cudaEvent_t e; cudaEventCreateWithFlags(&e, cudaEventDisableTiming); return e;
    }();
    static cudaEvent_t evGemm1 = [] {
        cudaEvent_t e; cudaEventCreateWithFlags(&e, cudaEventDisableTiming); return e;
    }();
    static cudaEvent_t evA = [] {
        cudaEvent_t e; cudaEventCreateWithFlags(&e, cudaEventDisableTiming); return e;
    }();
    static cudaEvent_t evS2 = [] {
        cudaEvent_t e; cudaEventCreateWithFlags(&e, cudaEventDisableTiming); return e;
    }();

    cudaStream_t s0 = 0;

    cudaEventRecord(evFork, s0);
    cudaStreamWaitEvent(s2, evFork, 0);

    // k_gemm1 (HMMA) is the 4th created kernel (ncu capture alignment)
    k_hist  <<<(NE + 255) / 256, 256, 0, s0>>>(ei + NE);                  // 1
    k_prew  <<<8, 256, 0, s2>>>(W1, a1s, a1d);                            // 2
    k_xcvt  <<<(NN + 7) / 8, 256, 0, s2>>>(x);                            // 3
    k_gemm1 <<<((NN + 127) / 128) * 4, 256, 0, s2>>>();                   // 4
    cudaEventRecord(evGemm1, s2);
    k_edgeA <<<(NE + 255) / 256, 256, 0, s2>>>(ea, We, be, out);          // 5
    k_scanA <<<NB, 256, 0, s0>>>();                                       // 6
    k_scanB <<<1, 256, 0, s0>>>();                                        // 7
    k_scanC <<<NB, 256, 0, s0>>>();                                       // 8
    k_scatter<<<(NT + 255) / 256, 256, 0, s0>>>(ei);                      // 9

    // tail: pipelined agg1 / gemm2 halves
    cudaStreamWaitEvent(s0, evGemm1, 0);
    k_agg1 <<<(NHALF * 32 + 255) / 256, 256, 0, s0>>>(b1, 0, NHALF);      // 10
    cudaEventRecord(evA, s0);
    k_agg1 <<<((NN - NHALF) * 32 + 255) / 256, 256, 0, s0>>>(b1, NHALF, NN); // 11
    cudaStreamWaitEvent(s2, evA, 0);
    k_gemm2<<<(NHALF + 63) / 64, 256, 0, s2>>>(W2, a2s, a2d, 0, NHALF);   // 12
    cudaEventRecord(evS2, s2);
    k_gemm2<<<(NN - NHALF + 63) / 64, 256, 0, s0>>>(W2, a2s, a2d, NHALF, NN - NHALF); // 13
    cudaStreamWaitEvent(s0, evS2, 0);
    k_agg2out<<<(NN * 32 + 255) / 256, 256, 0, s0>>>(b2, Wn, bn, We, out); // 14
    k_edgeB  <<<(NE + 255) / 256, 256, 0, s0>>>(ei, out);                  // 15
}

// round 16
// speedup vs baseline: 1.1578x; 1.0133x over previous
#include <cuda_runtime.h>
#include <cuda_fp16.h>
#include <math.h>

#define NN 50000
#define NE 800000
#define NT (NE + NN)
#define NB 196      // 196*256 = 50176 >= NN

// ---------------- scratch (static __device__, allocation-free) ----------------
__device__ __half g_xh  [NN * 64];   // x in fp16 (HMMA A operand)
__device__ __half g_w1h [256 * 64];  // W1 transposed fp16: g_w1h[n*64+k] = W1[k,n]
__device__ __half g_h1h [NN * 256];  // layer1 pre-agg features (fp16)
__device__ __half g_h1ah[NN * 256];  // layer1 output (post agg + b1 + elu), fp16
__device__ float  g_wt1[8 * 64];     // folded W1@a1 (4 src heads, 4 dst heads)
__device__ float  g_al1s[NN * 4];
__device__ float  g_al1d[NN * 4];
__device__ __half g_h2h [NN * 64];   // layer2 pre-agg features (fp16)
__device__ float  g_al2s[NN];
__device__ float  g_al2d[NN];
__device__ float  g_u[NN];           // dot(h2a[n], We[0:64])
__device__ float  g_v[NN];           // dot(h2a[n], We[64:128])
__device__ int    g_deg[NN];         // zero at entry; hist adds; scatter re-zeros
__device__ int    g_off[NN + 1];
__device__ int    g_cur[NN];
__device__ int    g_bsum[NB];
__device__ int    g_bbase[NB];
__device__ int    g_row[NT];         // CSR (by destination): source node per slot

__device__ __forceinline__ float lrelu(float v) { return v > 0.f ? v : 0.2f * v; }
__device__ __forceinline__ float elu1(float v)  { return v > 0.f ? v : expm1f(v); }

// packed 2xfp32 FMA (sm_103a f32x2 pipe; 2x FFMA throughput)
__device__ __forceinline__ float2 ffma2(float2 a, float2 b, float2 c) {
    float2 d;
    asm("fma.rn.f32x2 %0, %1, %2, %3;"
        : "=l"(reinterpret_cast<unsigned long long&>(d))
        : "l"(reinterpret_cast<unsigned long long&>(a)),
          "l"(reinterpret_cast<unsigned long long&>(b)),
          "l"(reinterpret_cast<unsigned long long&>(c)));
    return d;
}

// ------- fused: degree histogram + edge_attr output contribution -------
__global__ void k_histA(const int* __restrict__ col, const float* __restrict__ ea,
                        const float* __restrict__ We, const float* __restrict__ be,
                        float* __restrict__ out) {
    int e = blockIdx.x * blockDim.x + threadIdx.x;
    if (e >= NE) return;
    atomicAdd(&g_deg[col[e]], 1);
    const float4* eav = (const float4*)(ea + (size_t)e * 16);
    const float4* wev = (const float4*)(We + 128);
    float4 w0 = wev[0], w1 = wev[1], w2 = wev[2], w3 = wev[3];
    float4 e0 = eav[0], e1 = eav[1], e2 = eav[2], e3 = eav[3];
    float t = be[0];
    t += e0.x * w0.x + e0.y * w0.y + e0.z * w0.z + e0.w * w0.w;
    t += e1.x * w1.x + e1.y * w1.y + e1.z * w1.z + e1.w * w1.w;
    t += e2.x * w2.x + e2.y * w2.y + e2.z * w2.z + e2.w * w2.w;
    t += e3.x * w3.x + e3.y * w3.y + e3.z * w3.z + e3.w * w3.w;
    out[NN * 32 + e] = t;
}

__global__ void k_scanA() {   // deg[i]+1 accounts for the self-loop
    __shared__ int ss[256];
    int b = blockIdx.x, t = threadIdx.x, i = b * 256 + t;
    int d = (i < NN) ? (g_deg[i] + 1) : 0;
    ss[t] = d; __syncthreads();
    for (int o = 1; o < 256; o <<= 1) {
        int v = 0; if (t >= o) v = ss[t - o];
        __syncthreads();
        if (t >= o) ss[t] += v;
        __syncthreads();
    }
    if (i < NN) g_off[i] = ss[t] - d;
    if (t == 255) g_bsum[b] = ss[255];
}

__global__ void k_scanB() {
    __shared__ int ss[256];
    int t = threadIdx.x;
    int v = (t < NB) ? g_bsum[t] : 0;
    ss[t] = v; __syncthreads();
    for (int o = 1; o < 256; o <<= 1) {
        int u = 0; if (t >= o) u = ss[t - o];
        __syncthreads();
        if (t >= o) ss[t] += u;
        __syncthreads();
    }
    if (t < NB) g_bbase[t] = ss[t] - v;
    if (t == NB - 1) g_off[NN] = ss[t];
}

__global__ void k_scanC() {
    int b = blockIdx.x, i = b * 256 + threadIdx.x;
    if (i < NN) {
        int v = g_off[i] + g_bbase[b];
        g_off[i] = v; g_cur[i] = v;
    }
}

__global__ void k_scatter(const int* __restrict__ ei) {
    int e = blockIdx.x * blockDim.x + threadIdx.x;
    if (e >= NT) return;
    int r, c;
    if (e < NE) { r = ei[e]; c = ei[NE + e]; }
    else        { r = c = e - NE; g_deg[e - NE] = 0; }  // reset deg for next replay
    int pos = atomicAdd(&g_cur[c], 1);
    g_row[pos] = r;
}

// ------- prew: folded attention weights + fp16 transposed W1 -------
__global__ void k_prew(const float* __restrict__ W1, const float* __restrict__ a1s,
                       const float* __restrict__ a1d) {
    int t = blockIdx.x * 256 + threadIdx.x;   // 2048 threads
    if (t < 512) {
        int o = t >> 6, k = t & 63, hh = o & 3;
        const float* a = (o < 4) ? a1s : a1d;
        float s = 0.f;
#pragma unroll 8
        for (int c = 0; c < 64; c++) s += W1[k * 256 + hh * 64 + c] * a[hh * 64 + c];
        g_wt1[o * 64 + k] = s;
    }
    for (int i = t; i < 256 * 64; i += 2048) {
        int n = i >> 6, kk = i & 63;
        g_w1h[i] = __float2half_rn(W1[kk * 256 + n]);
    }
}

// ------- xcvt: x -> fp16 + fp32 al1 logits (warp per node) -------
__global__ __launch_bounds__(256) void k_xcvt(const float* __restrict__ x) {
    __shared__ float ws[8][65];
    int tid = threadIdx.x;
    for (int i = tid; i < 512; i += 256) ws[i >> 6][i & 63] = g_wt1[i];
    __syncthreads();
    int n = blockIdx.x * 8 + (tid >> 5);
    int lane = tid & 31;
    if (n >= NN) return;
    float2 xv = ((const float2*)(x + (size_t)n * 64))[lane];
    ((half2*)(g_xh + (size_t)n * 64))[lane] = __floats2half2_rn(xv.x, xv.y);
    float p[8];
#pragma unroll
    for (int o = 0; o < 8; o++)
        p[o] = xv.x * ws[o][2 * lane] + xv.y * ws[o][2 * lane + 1];
#pragma unroll
    for (int off = 16; off; off >>= 1)
#pragma unroll
        for (int o = 0; o < 8; o++) p[o] += __shfl_xor_sync(0xffffffffu, p[o], off);
    if (lane == 0) {
        *(float4*)&g_al1s[n * 4] = make_float4(p[0], p[1], p[2], p[3]);
        *(float4*)&g_al1d[n * 4] = make_float4(p[4], p[5], p[6], p[7]);
    }
}

// --- GEMM1 via HMMA: h1h = xh[N,64] @ W1[64,256], fp32 accum, fp16 out. ---
__global__ __launch_bounds__(256) void k_gemm1() {
    int tid = threadIdx.x, wid = tid >> 5, lane = tid & 31;
    int mb = blockIdx.x >> 2, cb = blockIdx.x & 3;
    int row0 = mb * 128 + wid * 16;
    int g = lane >> 2, q = lane & 3;
    int rowA = row0 + g, rowB = row0 + g + 8;
    bool okA = rowA < NN, okB = rowB < NN;
    const __half* xa = g_xh + (size_t)rowA * 64;
    const __half* xb = g_xh + (size_t)rowB * 64;

    float c[8][4];
#pragma unroll
    for (int nt = 0; nt < 8; nt++)
#pragma unroll
        for (int j = 0; j < 4; j++) c[nt][j] = 0.f;

#pragma unroll
    for (int kt = 0; kt < 4; kt++) {
        int kb = kt * 16 + 2 * q;
        unsigned a0 = 0, a1 = 0, a2 = 0, a3 = 0;
        if (okA) { a0 = *(const unsigned*)(xa + kb); a2 = *(const unsigned*)(xa + kb + 8); }
        if (okB) { a1 = *(const unsigned*)(xb + kb); a3 = *(const unsigned*)(xb + kb + 8); }
#pragma unroll
        for (int nt = 0; nt < 8; nt++) {
            int ncol = cb * 64 + nt * 8 + g;
            const __half* bp = g_w1h + ncol * 64 + kt * 16 + 2 * q;
            unsigned b0 = *(const unsigned*)bp;
            unsigned b1 = *(const unsigned*)(bp + 8);
            asm volatile(
                "mma.sync.aligned.m16n8k16.row.col.f32.f16.f16.f32 "
                "{%0,%1,%2,%3}, {%4,%5,%6,%7}, {%8,%9}, {%0,%1,%2,%3};"
                : "+f"(c[nt][0]), "+f"(c[nt][1]), "+f"(c[nt][2]), "+f"(c[nt][3])
                : "r"(a0), "r"(a1), "r"(a2), "r"(a3), "r"(b0), "r"(b1));
        }
    }
#pragma unroll
    for (int nt = 0; nt < 8; nt++) {
        int colb = cb * 64 + nt * 8 + 2 * q;
        if (okA) {
            __half2 h = __floats2half2_rn(c[nt][0], c[nt][1]);
            *(unsigned*)&g_h1h[(size_t)rowA * 256 + colb] = *(unsigned*)&h;
        }
        if (okB) {
            __half2 h = __floats2half2_rn(c[nt][2], c[nt][3]);
            *(unsigned*)&g_h1h[(size_t)rowB * 256 + colb] = *(unsigned*)&h;
        }
    }
}

// ------- layer-1 fused softmax + aggregation: 2 warps per node -------
// warp covers 128 columns (uint2 = 4 halfs per lane); each warp walks all edges.
__global__ void k_agg1(const float* __restrict__ b1) {
    int gw   = (blockIdx.x * blockDim.x + threadIdx.x) >> 5;
    int n    = gw >> 1;
    int half = gw & 1;
    int lane = threadIdx.x & 31;
    if (n >= NN) return;
    int s0 = g_off[n], s1 = g_off[n + 1];
    int c0 = half * 128 + lane * 4;   // this lane's 4 columns
    int h  = c0 >> 6;                  // head index
    float ad = g_al1d[n * 4 + h];

    float2 acc0 = {0, 0}, acc1 = {0, 0};
    float z = 0.f;
    int i = s0;
    for (; i + 8 <= s1; i += 8) {
        int rr[8]; float al[8]; uint2 w[8];
#pragma unroll
        for (int u = 0; u < 8; u++) rr[u] = g_row[i + u];
#pragma unroll
        for (int u = 0; u < 8; u++) al[u] = g_al1s[rr[u] * 4 + h];
#pragma unroll
        for (int u = 0; u < 8; u++)
            w[u] = *(const uint2*)(g_h1h + (size_t)rr[u] * 256 + c0);
#pragma unroll
        for (int u = 0; u < 8; u++) {
            float e = __expf(lrelu(al[u] + ad));
            z += e;
            float2 ev = make_float2(e, e);
            acc0 = ffma2(ev, __half22float2(*(const __half2*)&w[u].x), acc0);
            acc1 = ffma2(ev, __half22float2(*(const __half2*)&w[u].y), acc1);
        }
    }
    for (; i + 4 <= s1; i += 4) {
        int rr[4]; float al[4]; uint2 w[4];
#pragma unroll
        for (int u = 0; u < 4; u++) rr[u] = g_row[i + u];
#pragma unroll
        for (int u = 0; u < 4; u++) al[u] = g_al1s[rr[u] * 4 + h];
#pragma unroll
        for (int u = 0; u < 4; u++)
            w[u] = *(const uint2*)(g_h1h + (size_t)rr[u] * 256 + c0);
#pragma unroll
        for (int u = 0; u < 4; u++) {
            float e = __expf(lrelu(al[u] + ad));
            z += e;
            float2 ev = make_float2(e, e);
            acc0 = ffma2(ev, __half22float2(*(const __half2*)&w[u].x), acc0);
            acc1 = ffma2(ev, __half22float2(*(const __half2*)&w[u].y), acc1);
        }
    }
    for (; i < s1; i++) {
        int r = g_row[i];
        float al = g_al1s[r * 4 + h];
        uint2 w = *(const uint2*)(g_h1h + (size_t)r * 256 + c0);
        float e = __expf(lrelu(al + ad));
        z += e;
        float2 ev = make_float2(e, e);
        acc0 = ffma2(ev, __half22float2(*(const __half2*)&w.x), acc0);
        acc1 = ffma2(ev, __half22float2(*(const __half2*)&w.y), acc1);
    }
    float inv = 1.f / (z + 1e-16f);
    float4 bv = *(const float4*)(b1 + c0);
    __half2 o0 = __floats2half2_rn(elu1(acc0.x * inv + bv.x), elu1(acc0.y * inv + bv.y));
    __half2 o1 = __floats2half2_rn(elu1(acc1.x * inv + bv.z), elu1(acc1.y * inv + bv.w));
    uint2 u = make_uint2(*(unsigned*)&o0, *(unsigned*)&o1);
    *(uint2*)&g_h1ah[(size_t)n * 256 + c0] = u;
}

// ------- GEMM2: register-tiled 64x64 tile, K=256 in 4 chunks (fp16 in); fused al2 -
__global__ __launch_bounds__(256) void k_gemm2(const float* __restrict__ W2,
                                               const float* __restrict__ a2s,
                                               const float* __restrict__ a2d) {
    __shared__ __align__(16) float xT[64][68];
    __shared__ float4 wsm[64][16];
    int tid = threadIdx.x;
    int row0 = blockIdx.x * 64;
    int nrows = NN - row0; if (nrows > 64) nrows = 64;
    int ty = tid >> 4, txc = tid & 15;

    float2 acc[4][2];
#pragma unroll
    for (int r = 0; r < 4; r++) { acc[r][0] = make_float2(0.f, 0.f); acc[r][1] = make_float2(0.f, 0.f); }

    for (int kc = 0; kc < 4; kc++) {
        const float4* wg = (const float4*)W2;
        for (int i = tid; i < 64 * 16; i += 256) {
            int k = i >> 4, c4 = i & 15;
            wsm[k][c4] = wg[(kc * 64 + k) * 16 + c4];
        }
        // stage x chunk from fp16 h1ah (coalesced uint2 loads), transposed
        for (int i = tid; i < 1024; i += 256) {
            int row = i >> 4, j = i & 15;
            if (row < nrows) {
                uint2 v = *(const uint2*)(g_h1ah + (size_t)(row0 + row) * 256 + kc * 64 + j * 4);
                float2 f0 = __half22float2(*(const __half2*)&v.x);
                float2 f1 = __half22float2(*(const __half2*)&v.y);
                int k = j * 4;
                xT[k][row] = f0.x; xT[k + 1][row] = f0.y;
                xT[k + 2][row] = f1.x; xT[k + 3][row] = f1.y;
            }
        }
        __syncthreads();
#pragma unroll 8
        for (int k = 0; k < 64; k++) {
            float4 xv = *(const float4*)&xT[k][ty * 4];
            float4 wv = wsm[k][txc];
            float2 w01 = make_float2(wv.x, wv.y), w23 = make_float2(wv.z, wv.w);
            float xr[4] = {xv.x, xv.y, xv.z, xv.w};
#pragma unroll
            for (int r = 0; r < 4; r++) {
                float2 xx = make_float2(xr[r], xr[r]);
                acc[r][0] = ffma2(xx, w01, acc[r][0]);
                acc[r][1] = ffma2(xx, w23, acc[r][1]);
            }
        }
        __syncthreads();
    }

    int c0 = txc * 4;
    float asv[4], adv[4];
#pragma unroll
    for (int c = 0; c < 4; c++) { asv[c] = a2s[c0 + c]; adv[c] = a2d[c0 + c]; }
#pragma unroll
    for (int r = 0; r < 4; r++) {
        int row = ty * 4 + r;
        bool ok = row < nrows;
        float4 hv = make_float4(acc[r][0].x, acc[r][0].y, acc[r][1].x, acc[r][1].y);
        if (ok) {
            __half2 ha = __floats2half2_rn(hv.x, hv.y);
            __half2 hb = __floats2half2_rn(hv.z, hv.w);
            uint2 u = make_uint2(*(unsigned*)&ha, *(unsigned*)&hb);
            *(uint2*)&g_h2h[(size_t)(row0 + row) * 64 + c0] = u;
        }
        float ps = hv.x * asv[0] + hv.y * asv[1] + hv.z * asv[2] + hv.w * asv[3];
        float pd = hv.x * adv[0] + hv.y * adv[1] + hv.z * adv[2] + hv.w * adv[3];
#pragma unroll
        for (int off = 8; off; off >>= 1) {
            ps += __shfl_down_sync(0xffffffffu, ps, off);
            pd += __shfl_down_sync(0xffffffffu, pd, off);
        }
        if (txc == 0 && ok) { g_al2s[row0 + row] = ps; g_al2d[row0 + row] = pd; }
    }
}

// --- layer-2 fused softmax + agg + node output + edge factors (warp/node, fp16 h2) -
__global__ void k_agg2out(const float* __restrict__ b2, const float* __restrict__ Wn,
                          const float* __restrict__ bn, const float* __restrict__ We,
                          float* __restrict__ out) {
    int n    = (blockIdx.x * blockDim.x + threadIdx.x) >> 5;
    int lane = threadIdx.x & 31;
    if (n >= NN) return;
    int s0 = g_off[n], s1 = g_off[n + 1];
    float ad = g_al2d[n];

    float2 acc = {0.f, 0.f};
    float z = 0.f;
    int i = s0;
    for (; i + 8 <= s1; i += 8) {
        int rr[8]; float al[8]; unsigned hh[8];
#pragma unroll
        for (int u = 0; u < 8; u++) rr[u] = g_row[i + u];
#pragma unroll
        for (int u = 0; u < 8; u++) al[u] = g_al2s[rr[u]];
#pragma unroll
        for (int u = 0; u < 8; u++)
            hh[u] = *(const unsigned*)(g_h2h + (size_t)rr[u] * 64 + 2 * lane);
#pragma unroll
        for (int u = 0; u < 8; u++) {
            float e = __expf(lrelu(al[u] + ad));
            z += e;
            acc = ffma2(make_float2(e, e), __half22float2(*(const __half2*)&hh[u]), acc);
        }
    }
    for (; i + 4 <= s1; i += 4) {
        int rr[4]; float al[4]; unsigned hh[4];
#pragma unroll
        for (int u = 0; u < 4; u++) rr[u] = g_row[i + u];
#pragma unroll
        for (int u = 0; u < 4; u++) al[u] = g_al2s[rr[u]];
#pragma unroll
        for (int u = 0; u < 4; u++)
            hh[u] = *(const unsigned*)(g_h2h + (size_t)rr[u] * 64 + 2 * lane);
#pragma unroll
        for (int u = 0; u < 4; u++) {
            float e = __expf(lrelu(al[u] + ad));
            z += e;
            acc = ffma2(make_float2(e, e), __half22float2(*(const __half2*)&hh[u]), acc);
        }
    }
    for (; i < s1; i++) {
        int r = g_row[i];
        float al = g_al2s[r];
        unsigned hv = *(const unsigned*)(g_h2h + (size_t)r * 64 + 2 * lane);
        float e = __expf(lrelu(al + ad));
        z += e;
        acc = ffma2(make_float2(e, e), __half22float2(*(const __half2*)&hv), acc);
    }
    float inv = 1.f / (z + 1e-16f);
    float2 bv = ((const float2*)b2)[lane];
    float2 o;
    o.x = elu1(acc.x * inv + bv.x);
    o.y = elu1(acc.y * inv + bv.y);

    float2 we0 = ((const float2*)We)[lane];
    float2 we1 = ((const float2*)(We + 64))[lane];
    float up = o.x * we0.x + o.y * we0.y;
    float vp = o.x * we1.x + o.y * we1.y;
#pragma unroll
    for (int off = 16; off; off >>= 1) {
        up += __shfl_xor_sync(0xffffffffu, up, off);
        vp += __shfl_xor_sync(0xffffffffu, vp, off);
    }
    if (lane == 0) { g_u[n] = up; g_v[n] = vp; }

    float accn = bn[lane];
#pragma unroll
    for (int kk = 0; kk < 32; kk++) {
        float hx = __shfl_sync(0xffffffffu, o.x, kk);
        float hy = __shfl_sync(0xffffffffu, o.y, kk);
        accn = fmaf(hx, Wn[(2 * kk) * 32 + lane], accn);
        accn = fmaf(hy, Wn[(2 * kk + 1) * 32 + lane], accn);
    }
    out[n * 32 + lane] = accn;
}

// ------- edge output part B: add node factors -------
__global__ void k_edgeB(const int* __restrict__ ei, float* __restrict__ out) {
    int e = blockIdx.x * blockDim.x + threadIdx.x;
    if (e >= NE) return;
    int r = ei[e], c = ei[NE + e];
    out[NN * 32 + e] += g_u[r] + g_v[c];
}

// ---------------- launch ----------------
extern "C" void kernel_launch(void* const* d_in, const int* in_sizes, int n_in,
                              void* d_out, int out_size) {
    const float* x   = (const float*)d_in[0];
    const int*   ei  = (const int*)  d_in[1];
    const float* ea  = (const float*)d_in[2];
    const float* W1  = (const float*)d_in[3];
    const float* a1s = (const float*)d_in[4];
    const float* a1d = (const float*)d_in[5];
    const float* b1  = (const float*)d_in[6];
    const float* W2  = (const float*)d_in[7];
    const float* a2s = (const float*)d_in[8];
    const float* a2d = (const float*)d_in[9];
    const float* b2  = (const float*)d_in[10];
    const float* Wn  = (const float*)d_in[11];
    const float* bn  = (const float*)d_in[12];
    const float* We  = (const float*)d_in[13];
    const float* be  = (const float*)d_in[14];
    float* out = (float*)d_out;

    static cudaStream_t s2 = [] {
        cudaStream_t s; cudaStreamCreateWithFlags(&s, cudaStreamNonBlocking); return s;
    }();
    static cudaEvent_t evFork = [] {
        cudaEvent_t e; cudaEventCreateWithFlags(&e, cudaEventDisableTiming); return e;
    }();
    static cudaEvent_t evGemm1 = [] {
        cudaEvent_t e; cudaEventCreateWithFlags(&e, cudaEventDisableTiming); return e;
    }();

    cudaStream_t s0 = 0;

    cudaEventRecord(evFork, s0);
    cudaStreamWaitEvent(s2, evFork, 0);

    // k_gemm1 (HMMA) stays the 4th created kernel (ncu capture alignment)
    k_histA <<<(NE + 255) / 256, 256, 0, s0>>>(ei + NE, ea, We, be, out); // 1
    k_prew  <<<8, 256, 0, s2>>>(W1, a1s, a1d);                            // 2
    k_xcvt  <<<(NN + 7) / 8, 256, 0, s2>>>(x);                            // 3
    k_gemm1 <<<((NN + 127) / 128) * 4, 256, 0, s2>>>();                   // 4
    cudaEventRecord(evGemm1, s2);
    k_scanA <<<NB, 256, 0, s0>>>();                                       // 5
    k_scanB <<<1, 256, 0, s0>>>();                                        // 6
    k_scanC <<<NB, 256, 0, s0>>>();                                       // 7
    k_scatter<<<(NT + 255) / 256, 256, 0, s0>>>(ei);                      // 8

    // tail (all on s0)
    cudaStreamWaitEvent(s0, evGemm1, 0);
    k_agg1   <<<(NN * 2 * 32) / 256, 256, 0, s0>>>(b1);                   // 9  (12500 blocks exact)
    k_gemm2  <<<(NN + 63) / 64, 256, 0, s0>>>(W2, a2s, a2d);              // 10
    k_agg2out<<<(NN * 32 + 255) / 256, 256, 0, s0>>>(b2, Wn, bn, We, out); // 11
    k_edgeB  <<<(NE + 255) / 256, 256, 0, s0>>>(ei, out);                  // 12
}

// round 17
// speedup vs baseline: 1.1694x; 1.0101x over previous
#include <cuda_runtime.h>
#include <cuda_fp16.h>
#include <math.h>

#define NN 50000
#define NE 800000
#define NT (NE + NN)
#define NB 196      // 196*256 = 50176 >= NN
#define NHALF 24992 // node split for tail pipelining

// ---------------- scratch (static __device__, allocation-free) ----------------
__device__ __half g_xh  [NN * 64];   // x in fp16 (HMMA A operand)
__device__ __half g_w1h [256 * 64];  // W1 transposed fp16: g_w1h[n*64+k] = W1[k,n]
__device__ __half g_h1h [NN * 256];  // layer1 pre-agg features (fp16)
__device__ __half g_h1ah[NN * 256];  // layer1 output (post agg + b1 + elu), fp16
__device__ float  g_wt1[8 * 64];     // folded W1@a1 (4 src heads, 4 dst heads)
__device__ float  g_al1s[NN * 4];
__device__ float  g_al1d[NN * 4];
__device__ __half g_h2h [NN * 64];   // layer2 pre-agg features (fp16)
__device__ float  g_al2s[NN];
__device__ float  g_al2d[NN];
__device__ float  g_u[NN];           // dot(h2a[n], We[0:64])
__device__ float  g_v[NN];           // dot(h2a[n], We[64:128])
__device__ int    g_deg[NN];         // zero at entry; hist adds; scatter re-zeros
__device__ int    g_off[NN + 1];
__device__ int    g_cur[NN];
__device__ int    g_bsum[NB];
__device__ int    g_bbase[NB];
__device__ int    g_row[NT];         // CSR (by destination): source node per slot

__device__ __forceinline__ float lrelu(float v) { return v > 0.f ? v : 0.2f * v; }
__device__ __forceinline__ float elu1(float v)  { return v > 0.f ? v : expm1f(v); }

// packed 2xfp32 FMA (sm_103a f32x2 pipe; 2x FFMA throughput)
__device__ __forceinline__ float2 ffma2(float2 a, float2 b, float2 c) {
    float2 d;
    asm("fma.rn.f32x2 %0, %1, %2, %3;"
        : "=l"(reinterpret_cast<unsigned long long&>(d))
        : "l"(reinterpret_cast<unsigned long long&>(a)),
          "l"(reinterpret_cast<unsigned long long&>(b)),
          "l"(reinterpret_cast<unsigned long long&>(c)));
    return d;
}

// ------- fused: degree histogram + edge_attr output contribution -------
__global__ void k_histA(const int* __restrict__ col, const float* __restrict__ ea,
                        const float* __restrict__ We, const float* __restrict__ be,
                        float* __restrict__ out) {
    int e = blockIdx.x * blockDim.x + threadIdx.x;
    if (e >= NE) return;
    atomicAdd(&g_deg[col[e]], 1);
    const float4* eav = (const float4*)(ea + (size_t)e * 16);
    const float4* wev = (const float4*)(We + 128);
    float4 w0 = wev[0], w1 = wev[1], w2 = wev[2], w3 = wev[3];
    float4 e0 = eav[0], e1 = eav[1], e2 = eav[2], e3 = eav[3];
    float t = be[0];
    t += e0.x * w0.x + e0.y * w0.y + e0.z * w0.z + e0.w * w0.w;
    t += e1.x * w1.x + e1.y * w1.y + e1.z * w1.z + e1.w * w1.w;
    t += e2.x * w2.x + e2.y * w2.y + e2.z * w2.z + e2.w * w2.w;
    t += e3.x * w3.x + e3.y * w3.y + e3.z * w3.z + e3.w * w3.w;
    out[NN * 32 + e] = t;
}

__global__ void k_scanA() {   // deg[i]+1 accounts for the self-loop
    __shared__ int ss[256];
    int b = blockIdx.x, t = threadIdx.x, i = b * 256 + t;
    int d = (i < NN) ? (g_deg[i] + 1) : 0;
    ss[t] = d; __syncthreads();
    for (int o = 1; o < 256; o <<= 1) {
        int v = 0; if (t >= o) v = ss[t - o];
        __syncthreads();
        if (t >= o) ss[t] += v;
        __syncthreads();
    }
    if (i < NN) g_off[i] = ss[t] - d;
    if (t == 255) g_bsum[b] = ss[255];
}

__global__ void k_scanB() {
    __shared__ int ss[256];
    int t = threadIdx.x;
    int v = (t < NB) ? g_bsum[t] : 0;
    ss[t] = v; __syncthreads();
    for (int o = 1; o < 256; o <<= 1) {
        int u = 0; if (t >= o) u = ss[t - o];
        __syncthreads();
        if (t >= o) ss[t] += u;
        __syncthreads();
    }
    if (t < NB) g_bbase[t] = ss[t] - v;
    if (t == NB - 1) g_off[NN] = ss[t];
}

__global__ void k_scanC() {
    int b = blockIdx.x, i = b * 256 + threadIdx.x;
    if (i < NN) {
        int v = g_off[i] + g_bbase[b];
        g_off[i] = v; g_cur[i] = v;
    }
}

__global__ void k_scatter(const int* __restrict__ ei) {
    int e = blockIdx.x * blockDim.x + threadIdx.x;
    if (e >= NT) return;
    int r, c;
    if (e < NE) { r = ei[e]; c = ei[NE + e]; }
    else        { r = c = e - NE; g_deg[e - NE] = 0; }  // reset deg for next replay
    int pos = atomicAdd(&g_cur[c], 1);
    g_row[pos] = r;
}

// ------- prew: folded attention weights + fp16 transposed W1 -------
__global__ void k_prew(const float* __restrict__ W1, const float* __restrict__ a1s,
                       const float* __restrict__ a1d) {
    int t = blockIdx.x * 256 + threadIdx.x;   // 2048 threads
    if (t < 512) {
        int o = t >> 6, k = t & 63, hh = o & 3;
        const float* a = (o < 4) ? a1s : a1d;
        float s = 0.f;
#pragma unroll 8
        for (int c = 0; c < 64; c++) s += W1[k * 256 + hh * 64 + c] * a[hh * 64 + c];
        g_wt1[o * 64 + k] = s;
    }
    for (int i = t; i < 256 * 64; i += 2048) {
        int n = i >> 6, kk = i & 63;
        g_w1h[i] = __float2half_rn(W1[kk * 256 + n]);
    }
}

// ------- xcvt: x -> fp16 + fp32 al1 logits (warp per node) -------
__global__ __launch_bounds__(256) void k_xcvt(const float* __restrict__ x) {
    __shared__ float ws[8][65];
    int tid = threadIdx.x;
    for (int i = tid; i < 512; i += 256) ws[i >> 6][i & 63] = g_wt1[i];
    __syncthreads();
    int n = blockIdx.x * 8 + (tid >> 5);
    int lane = tid & 31;
    if (n >= NN) return;
    float2 xv = ((const float2*)(x + (size_t)n * 64))[lane];
    ((half2*)(g_xh + (size_t)n * 64))[lane] = __floats2half2_rn(xv.x, xv.y);
    float p[8];
#pragma unroll
    for (int o = 0; o < 8; o++)
        p[o] = xv.x * ws[o][2 * lane] + xv.y * ws[o][2 * lane + 1];
#pragma unroll
    for (int off = 16; off; off >>= 1)
#pragma unroll
        for (int o = 0; o < 8; o++) p[o] += __shfl_xor_sync(0xffffffffu, p[o], off);
    if (lane == 0) {
        *(float4*)&g_al1s[n * 4] = make_float4(p[0], p[1], p[2], p[3]);
        *(float4*)&g_al1d[n * 4] = make_float4(p[4], p[5], p[6], p[7]);
    }
}

// --- GEMM1 via HMMA: h1h = xh[N,64] @ W1[64,256], fp32 accum, fp16 out. ---
__global__ __launch_bounds__(256) void k_gemm1() {
    int tid = threadIdx.x, wid = tid >> 5, lane = tid & 31;
    int mb = blockIdx.x >> 2, cb = blockIdx.x & 3;
    int row0 = mb * 128 + wid * 16;
    int g = lane >> 2, q = lane & 3;
    int rowA = row0 + g, rowB = row0 + g + 8;
    bool okA = rowA < NN, okB = rowB < NN;
    const __half* xa = g_xh + (size_t)rowA * 64;
    const __half* xb = g_xh + (size_t)rowB * 64;

    float c[8][4];
#pragma unroll
    for (int nt = 0; nt < 8; nt++)
#pragma unroll
        for (int j = 0; j < 4; j++) c[nt][j] = 0.f;

#pragma unroll
    for (int kt = 0; kt < 4; kt++) {
        int kb = kt * 16 + 2 * q;
        unsigned a0 = 0, a1 = 0, a2 = 0, a3 = 0;
        if (okA) { a0 = *(const unsigned*)(xa + kb); a2 = *(const unsigned*)(xa + kb + 8); }
        if (okB) { a1 = *(const unsigned*)(xb + kb); a3 = *(const unsigned*)(xb + kb + 8); }
#pragma unroll
        for (int nt = 0; nt < 8; nt++) {
            int ncol = cb * 64 + nt * 8 + g;
            const __half* bp = g_w1h + ncol * 64 + kt * 16 + 2 * q;
            unsigned b0 = *(const unsigned*)bp;
            unsigned b1 = *(const unsigned*)(bp + 8);
            asm volatile(
                "mma.sync.aligned.m16n8k16.row.col.f32.f16.f16.f32 "
                "{%0,%1,%2,%3}, {%4,%5,%6,%7}, {%8,%9}, {%0,%1,%2,%3};"
                : "+f"(c[nt][0]), "+f"(c[nt][1]), "+f"(c[nt][2]), "+f"(c[nt][3])
                : "r"(a0), "r"(a1), "r"(a2), "r"(a3), "r"(b0), "r"(b1));
        }
    }
#pragma unroll
    for (int nt = 0; nt < 8; nt++) {
        int colb = cb * 64 + nt * 8 + 2 * q;
        if (okA) {
            __half2 h = __floats2half2_rn(c[nt][0], c[nt][1]);
            *(unsigned*)&g_h1h[(size_t)rowA * 256 + colb] = *(unsigned*)&h;
        }
        if (okB) {
            __half2 h = __floats2half2_rn(c[nt][2], c[nt][3]);
            *(unsigned*)&g_h1h[(size_t)rowB * 256 + colb] = *(unsigned*)&h;
        }
    }
}

// ------- layer-1 fused softmax + aggregation (1 warp/node, uint4 fp16 loads) -----
__global__ void k_agg1(const float* __restrict__ b1, int n0, int n1) {
    int n    = n0 + ((blockIdx.x * blockDim.x + threadIdx.x) >> 5);
    int lane = threadIdx.x & 31;
    if (n >= n1) return;
    int s0 = g_off[n], s1 = g_off[n + 1];
    int h = lane >> 3;  // lane's 8 columns [lane*8, lane*8+8) in head h
    float ad = g_al1d[n * 4 + h];

    float2 acc[4] = {{0,0},{0,0},{0,0},{0,0}};
    float z = 0.f;
    int i = s0;
    for (; i + 8 <= s1; i += 8) {
        int rr[8]; float al[8]; uint4 w[8];
#pragma unroll
        for (int u = 0; u < 8; u++) rr[u] = g_row[i + u];
#pragma unroll
        for (int u = 0; u < 8; u++) al[u] = g_al1s[rr[u] * 4 + h];
#pragma unroll
        for (int u = 0; u < 8; u++)
            w[u] = *(const uint4*)(g_h1h + (size_t)rr[u] * 256 + lane * 8);
#pragma unroll
        for (int u = 0; u < 8; u++) {
            float e = __expf(lrelu(al[u] + ad));
            z += e;
            float2 ev = make_float2(e, e);
            acc[0] = ffma2(ev, __half22float2(*(const __half2*)&w[u].x), acc[0]);
            acc[1] = ffma2(ev, __half22float2(*(const __half2*)&w[u].y), acc[1]);
            acc[2] = ffma2(ev, __half22float2(*(const __half2*)&w[u].z), acc[2]);
            acc[3] = ffma2(ev, __half22float2(*(const __half2*)&w[u].w), acc[3]);
        }
    }
    for (; i + 4 <= s1; i += 4) {
        int rr[4]; float al[4]; uint4 w[4];
#pragma unroll
        for (int u = 0; u < 4; u++) rr[u] = g_row[i + u];
#pragma unroll
        for (int u = 0; u < 4; u++) al[u] = g_al1s[rr[u] * 4 + h];
#pragma unroll
        for (int u = 0; u < 4; u++)
            w[u] = *(const uint4*)(g_h1h + (size_t)rr[u] * 256 + lane * 8);
#pragma unroll
        for (int u = 0; u < 4; u++) {
            float e = __expf(lrelu(al[u] + ad));
            z += e;
            float2 ev = make_float2(e, e);
            acc[0] = ffma2(ev, __half22float2(*(const __half2*)&w[u].x), acc[0]);
            acc[1] = ffma2(ev, __half22float2(*(const __half2*)&w[u].y), acc[1]);
            acc[2] = ffma2(ev, __half22float2(*(const __half2*)&w[u].z), acc[2]);
            acc[3] = ffma2(ev, __half22float2(*(const __half2*)&w[u].w), acc[3]);
        }
    }
    for (; i < s1; i++) {
        int r = g_row[i];
        float al = g_al1s[r * 4 + h];
        uint4 w = *(const uint4*)(g_h1h + (size_t)r * 256 + lane * 8);
        float e = __expf(lrelu(al + ad));
        z += e;
        float2 ev = make_float2(e, e);
        acc[0] = ffma2(ev, __half22float2(*(const __half2*)&w.x), acc[0]);
        acc[1] = ffma2(ev, __half22float2(*(const __half2*)&w.y), acc[1]);
        acc[2] = ffma2(ev, __half22float2(*(const __half2*)&w.z), acc[2]);
        acc[3] = ffma2(ev, __half22float2(*(const __half2*)&w.w), acc[3]);
    }
    float inv = 1.f / (z + 1e-16f);
    float4 bv0 = *(const float4*)(b1 + lane * 8);
    float4 bv1 = *(const float4*)(b1 + lane * 8 + 4);
    __half2 o0 = __floats2half2_rn(elu1(acc[0].x * inv + bv0.x), elu1(acc[0].y * inv + bv0.y));
    __half2 o1 = __floats2half2_rn(elu1(acc[1].x * inv + bv0.z), elu1(acc[1].y * inv + bv0.w));
    __half2 o2 = __floats2half2_rn(elu1(acc[2].x * inv + bv1.x), elu1(acc[2].y * inv + bv1.y));
    __half2 o3 = __floats2half2_rn(elu1(acc[3].x * inv + bv1.z), elu1(acc[3].y * inv + bv1.w));
    uint4 u = make_uint4(*(unsigned*)&o0, *(unsigned*)&o1, *(unsigned*)&o2, *(unsigned*)&o3);
    *(uint4*)&g_h1ah[(size_t)n * 256 + lane * 8] = u;
}

// ------- GEMM2: register-tiled 64x64 tile, K=256 in 4 chunks (fp16 in); fused al2 -
__global__ __launch_bounds__(256) void k_gemm2(const float* __restrict__ W2,
                                               const float* __restrict__ a2s,
                                               const float* __restrict__ a2d,
                                               int base, int count) {
    __shared__ __align__(16) float xT[64][68];
    __shared__ float4 wsm[64][16];
    int tid = threadIdx.x;
    int row0 = base + blockIdx.x * 64;
    int nrows = base + count - row0; if (nrows > 64) nrows = 64;
    int ty = tid >> 4, txc = tid & 15;

    float2 acc[4][2];
#pragma unroll
    for (int r = 0; r < 4; r++) { acc[r][0] = make_float2(0.f, 0.f); acc[r][1] = make_float2(0.f, 0.f); }

    for (int kc = 0; kc < 4; kc++) {
        const float4* wg = (const float4*)W2;
        for (int i = tid; i < 64 * 16; i += 256) {
            int k = i >> 4, c4 = i & 15;
            wsm[k][c4] = wg[(kc * 64 + k) * 16 + c4];
        }
        for (int i = tid; i < 1024; i += 256) {
            int row = i >> 4, j = i & 15;
            if (row < nrows) {
                uint2 v = *(const uint2*)(g_h1ah + (size_t)(row0 + row) * 256 + kc * 64 + j * 4);
                float2 f0 = __half22float2(*(const __half2*)&v.x);
                float2 f1 = __half22float2(*(const __half2*)&v.y);
                int k = j * 4;
                xT[k][row] = f0.x; xT[k + 1][row] = f0.y;
                xT[k + 2][row] = f1.x; xT[k + 3][row] = f1.y;
            }
        }
        __syncthreads();
#pragma unroll 8
        for (int k = 0; k < 64; k++) {
            float4 xv = *(const float4*)&xT[k][ty * 4];
            float4 wv = wsm[k][txc];
            float2 w01 = make_float2(wv.x, wv.y), w23 = make_float2(wv.z, wv.w);
            float xr[4] = {xv.x, xv.y, xv.z, xv.w};
#pragma unroll
            for (int r = 0; r < 4; r++) {
                float2 xx = make_float2(xr[r], xr[r]);
                acc[r][0] = ffma2(xx, w01, acc[r][0]);
                acc[r][1] = ffma2(xx, w23, acc[r][1]);
            }
        }
        __syncthreads();
    }

    int c0 = txc * 4;
    float asv[4], adv[4];
#pragma unroll
    for (int c = 0; c < 4; c++) { asv[c] = a2s[c0 + c]; adv[c] = a2d[c0 + c]; }
#pragma unroll
    for (int r = 0; r < 4; r++) {
        int row = ty * 4 + r;
        bool ok = row < nrows;
        float4 hv = make_float4(acc[r][0].x, acc[r][0].y, acc[r][1].x, acc[r][1].y);
        if (ok) {
            __half2 ha = __floats2half2_rn(hv.x, hv.y);
            __half2 hb = __floats2half2_rn(hv.z, hv.w);
            uint2 u = make_uint2(*(unsigned*)&ha, *(unsigned*)&hb);
            *(uint2*)&g_h2h[(size_t)(row0 + row) * 64 + c0] = u;
        }
        float ps = hv.x * asv[0] + hv.y * asv[1] + hv.z * asv[2] + hv.w * asv[3];
        float pd = hv.x * adv[0] + hv.y * adv[1] + hv.z * adv[2] + hv.w * adv[3];
#pragma unroll
        for (int off = 8; off; off >>= 1) {
            ps += __shfl_down_sync(0xffffffffu, ps, off);
            pd += __shfl_down_sync(0xffffffffu, pd, off);
        }
        if (txc == 0 && ok) { g_al2s[row0 + row] = ps; g_al2d[row0 + row] = pd; }
    }
}

// --- layer-2 fused softmax + agg + node output + edge factors (warp/node, fp16 h2) -
__global__ void k_agg2out(const float* __restrict__ b2, const float* __restrict__ Wn,
                          const float* __restrict__ bn, const float* __restrict__ We,
                          float* __restrict__ out) {
    int n    = (blockIdx.x * blockDim.x + threadIdx.x) >> 5;
    int lane = threadIdx.x & 31;
    if (n >= NN) return;
    int s0 = g_off[n], s1 = g_off[n + 1];
    float ad = g_al2d[n];

    float2 acc = {0.f, 0.f};
    float z = 0.f;
    int i = s0;
    for (; i + 8 <= s1; i += 8) {
        int rr[8]; float al[8]; unsigned hh[8];
#pragma unroll
        for (int u = 0; u < 8; u++) rr[u] = g_row[i + u];
#pragma unroll
        for (int u = 0; u < 8; u++) al[u] = g_al2s[rr[u]];
#pragma unroll
        for (int u = 0; u < 8; u++)
            hh[u] = *(const unsigned*)(g_h2h + (size_t)rr[u] * 64 + 2 * lane);
#pragma unroll
        for (int u = 0; u < 8; u++) {
            float e = __expf(lrelu(al[u] + ad));
            z += e;
            acc = ffma2(make_float2(e, e), __half22float2(*(const __half2*)&hh[u]), acc);
        }
    }
    for (; i + 4 <= s1; i += 4) {
        int rr[4]; float al[4]; unsigned hh[4];
#pragma unroll
        for (int u = 0; u < 4; u++) rr[u] = g_row[i + u];
#pragma unroll
        for (int u = 0; u < 4; u++) al[u] = g_al2s[rr[u]];
#pragma unroll
        for (int u = 0; u < 4; u++)
            hh[u] = *(const unsigned*)(g_h2h + (size_t)rr[u] * 64 + 2 * lane);
#pragma unroll
        for (int u = 0; u < 4; u++) {
            float e = __expf(lrelu(al[u] + ad));
            z += e;
            acc = ffma2(make_float2(e, e), __half22float2(*(const __half2*)&hh[u]), acc);
        }
    }
    for (; i < s1; i++) {
        int r = g_row[i];
        float al = g_al2s[r];
        unsigned hv = *(const unsigned*)(g_h2h + (size_t)r * 64 + 2 * lane);
        float e = __expf(lrelu(al + ad));
        z += e;
        acc = ffma2(make_float2(e, e), __half22float2(*(const __half2*)&hv), acc);
    }
    float inv = 1.f / (z + 1e-16f);
    float2 bv = ((const float2*)b2)[lane];
    float2 o;
    o.x = elu1(acc.x * inv + bv.x);
    o.y = elu1(acc.y * inv + bv.y);

    float2 we0 = ((const float2*)We)[lane];
    float2 we1 = ((const float2*)(We + 64))[lane];
    float up = o.x * we0.x + o.y * we0.y;
    float vp = o.x * we1.x + o.y * we1.y;
#pragma unroll
    for (int off = 16; off; off >>= 1) {
        up += __shfl_xor_sync(0xffffffffu, up, off);
        vp += __shfl_xor_sync(0xffffffffu, vp, off);
    }
    if (lane == 0) { g_u[n] = up; g_v[n] = vp; }

    float accn = bn[lane];
#pragma unroll
    for (int kk = 0; kk < 32; kk++) {
        float hx = __shfl_sync(0xffffffffu, o.x, kk);
        float hy = __shfl_sync(0xffffffffu, o.y, kk);
        accn = fmaf(hx, Wn[(2 * kk) * 32 + lane], accn);
        accn = fmaf(hy, Wn[(2 * kk + 1) * 32 + lane], accn);
    }
    out[n * 32 + lane] = accn;
}

// ------- edge output part B: add node factors -------
__global__ void k_edgeB(const int* __restrict__ ei, float* __restrict__ out) {
    int e = blockIdx.x * blockDim.x + threadIdx.x;
    if (e >= NE) return;
    int r = ei[e], c = ei[NE + e];
    out[NN * 32 + e] += g_u[r] + g_v[c];
}

// ---------------- launch ----------------
extern "C" void kernel_launch(void* const* d_in, const int* in_sizes, int n_in,
                              void* d_out, int out_size) {
    const float* x   = (const float*)d_in[0];
    const int*   ei  = (const int*)  d_in[1];
    const float* ea  = (const float*)d_in[2];
    const float* W1  = (const float*)d_in[3];
    const float* a1s = (const float*)d_in[4];
    const float* a1d = (const float*)d_in[5];
    const float* b1  = (const float*)d_in[6];
    const float* W2  = (const float*)d_in[7];
    const float* a2s = (const float*)d_in[8];
    const float* a2d = (const float*)d_in[9];
    const float* b2  = (const float*)d_in[10];
    const float* Wn  = (const float*)d_in[11];
    const float* bn  = (const float*)d_in[12];
    const float* We  = (const float*)d_in[13];
    const float* be  = (const float*)d_in[14];
    float* out = (float*)d_out;

    static cudaStream_t s2 = [] {
        cudaStream_t s; cudaStreamCreateWithFlags(&s, cudaStreamNonBlocking); return s;
    }();
    static cudaEvent_t evFork = [] {
        cudaEvent_t e; cudaEventCreateWithFlags(&e, cudaEventDisableTiming); return e;
    }();
    static cudaEvent_t evGemm1 = [] {
        cudaEvent_t e; cudaEventCreateWithFlags(&e, cudaEventDisableTiming); return e;
    }();
    static cudaEvent_t evA = [] {
        cudaEvent_t e; cudaEventCreateWithFlags(&e, cudaEventDisableTiming); return e;
    }();
    static cudaEvent_t evS2 = [] {
        cudaEvent_t e; cudaEventCreateWithFlags(&e, cudaEventDisableTiming); return e;
    }();

    cudaStream_t s0 = 0;

    cudaEventRecord(evFork, s0);
    cudaStreamWaitEvent(s2, evFork, 0);

    // k_gemm1 (HMMA) stays the 4th created kernel (ncu capture alignment)
    k_histA <<<(NE + 255) / 256, 256, 0, s0>>>(ei + NE, ea, We, be, out); // 1
    k_prew  <<<8, 256, 0, s2>>>(W1, a1s, a1d);                            // 2
    k_xcvt  <<<(NN + 7) / 8, 256, 0, s2>>>(x);                            // 3
    k_gemm1 <<<((NN + 127) / 128) * 4, 256, 0, s2>>>();                   // 4
    cudaEventRecord(evGemm1, s2);
    k_scanA <<<NB, 256, 0, s0>>>();                                       // 5
    k_scanB <<<1, 256, 0, s0>>>();                                        // 6
    k_scanC <<<NB, 256, 0, s0>>>();                                       // 7
    k_scatter<<<(NT + 255) / 256, 256, 0, s0>>>(ei);                      // 8

    // tail: pipelined agg1 / gemm2 halves
    cudaStreamWaitEvent(s0, evGemm1, 0);
    k_agg1 <<<(NHALF * 32 + 255) / 256, 256, 0, s0>>>(b1, 0, NHALF);      // 9
    cudaEventRecord(evA, s0);
    k_agg1 <<<((NN - NHALF) * 32 + 255) / 256, 256, 0, s0>>>(b1, NHALF, NN); // 10
    cudaStreamWaitEvent(s2, evA, 0);
    k_gemm2<<<(NHALF + 63) / 64, 256, 0, s2>>>(W2, a2s, a2d, 0, NHALF);   // 11
    cudaEventRecord(evS2, s2);
    k_gemm2<<<(NN - NHALF + 63) / 64, 256, 0, s0>>>(W2, a2s, a2d, NHALF, NN - NHALF); // 12
    cudaStreamWaitEvent(s0, evS2, 0);
    k_agg2out<<<(NN * 32 + 255) / 256, 256, 0, s0>>>(b2, Wn, bn, We, out); // 13
    k_edgeB  <<<(NE + 255) / 256, 256, 0, s0>>>(ei, out);                  // 14
}